// round 9
// baseline (speedup 1.0000x reference)
#include <cuda_runtime.h>
#include <cuda_bf16.h>
#include <cuda_fp16.h>
#include <math.h>
#include <stdint.h>

#define N_NODES 100000
#define N_EDGES 1600000
#define DIN 64
#define DHID 128
#define DOUT 40
#define Y2L_W32 24  // y2l row stride in uint32 (48 halves = 96B = 3 sectors)
#define SCAN_B 512
#define SCAN_NB ((N_NODES + SCAN_B - 1) / SCAN_B)
#define TILE_M 128
#define N_TILES ((N_NODES + TILE_M - 1) / TILE_M)  // 782
#define W2ROWS 80
#define LDS_ROW 136  // bf16 elems per SMEM row (128 + 8 pad) -> conflict-free frags

// SMEM byte offsets for fused kernel
#define SM_AH 0
#define SM_AL 34816
#define SM_W1H 69632
#define SM_W1L 104448
#define SM_W2H 139264
#define SM_W2L 161024
#define SM_BIAS 182784
#define SM_TOTAL 183424

// ---------------- device scratch ----------------
__device__ int g_is64;
__device__ int g_deg[N_NODES];
__device__ int g_rowptr[N_NODES + 1];
__device__ int g_fill[N_NODES];
__device__ int g_col[N_EDGES];
__device__ int g_part[256];
__device__ uint32_t g_xh[(size_t)N_NODES * 32];  // x as half2 pairs [node][32]
__device__ uint32_t g_w1h[DHID * 64], g_w1l[DHID * 64];      // [128 out][128 k] bf16x2
__device__ uint32_t g_w2h[W2ROWS * 64], g_w2l[W2ROWS * 64];  // [80 out][128 k]
__device__ uint32_t g_y2l[(size_t)N_NODES * Y2L_W32 + 32];   // half2, padded tail
__device__ float g_y2r[(size_t)N_NODES * DOUT];

// ---------------- helpers ----------------
__device__ __forceinline__ void mma16816(float* c, const uint32_t* a,
                                         uint32_t b0, uint32_t b1) {
    asm volatile(
        "mma.sync.aligned.m16n8k16.row.col.f32.bf16.bf16.f32 "
        "{%0,%1,%2,%3}, {%4,%5,%6,%7}, {%8,%9}, {%0,%1,%2,%3};"
        : "+f"(c[0]), "+f"(c[1]), "+f"(c[2]), "+f"(c[3])
        : "r"(a[0]), "r"(a[1]), "r"(a[2]), "r"(a[3]), "r"(b0), "r"(b1));
}
__device__ __forceinline__ void split_bf16(float v, __nv_bfloat16& h, __nv_bfloat16& l) {
    h = __float2bfloat16_rn(v);
    l = __float2bfloat16_rn(v - __bfloat162float(h));
}
__device__ __forceinline__ uint32_t pack_bf2(__nv_bfloat16 a, __nv_bfloat16 b) {
    __nv_bfloat162 p = __nv_bfloat162(a, b);
    return *(uint32_t*)&p;
}

// ---------------- edge index access (int64 or int32, runtime-detected) ----
__device__ __forceinline__ int edst(const void* ei, int e) {
    return g_is64 ? (int)((const long long*)ei)[(size_t)N_EDGES + e]
                  : ((const int*)ei)[(size_t)N_EDGES + e];
}
__device__ __forceinline__ int esrc(const void* ei, int e) {
    return g_is64 ? (int)((const long long*)ei)[e] : ((const int*)ei)[e];
}

// init degrees + dtype detect + weight split + x->fp16 conversion
__global__ void k_init(const int* ei, const float* __restrict__ x,
                       const float* __restrict__ W1l, const float* __restrict__ W1r,
                       const float* __restrict__ W2l, const float* __restrict__ W2r) {
    int i = blockIdx.x * blockDim.x + threadIdx.x;
    if (i < N_NODES) g_deg[i] = 0;
    if (i < N_NODES * 32) {
        int n = i >> 5, q = i & 31;
        float2 v = *(const float2*)&x[(size_t)n * DIN + 2 * q];
        __half2 h = __floats2half2_rn(v.x, v.y);
        g_xh[(size_t)n * 32 + q] = *(uint32_t*)&h;
    }
    int tot1 = DHID * 64;
    if (i < tot1) {
        int o = i >> 6, c = 2 * (i & 63);
        float v0 = (c < 64) ? W1l[o * 64 + c] : W1r[o * 64 + c - 64];
        float v1 = (c < 64) ? W1l[o * 64 + c + 1] : W1r[o * 64 + c - 63];
        __nv_bfloat16 h0, h1, l0, l1;
        split_bf16(v0, h0, l0); split_bf16(v1, h1, l1);
        g_w1h[i] = pack_bf2(h0, h1);
        g_w1l[i] = pack_bf2(l0, l1);
    } else if (i < tot1 + W2ROWS * 64) {
        int j = i - tot1;
        int o = j >> 6, c = 2 * (j & 63);
        float v0 = (o < DOUT) ? W2l[o * DHID + c] : W2r[(o - DOUT) * DHID + c];
        float v1 = (o < DOUT) ? W2l[o * DHID + c + 1] : W2r[(o - DOUT) * DHID + c + 1];
        __nv_bfloat16 h0, h1, l0, l1;
        split_bf16(v0, h0, l0); split_bf16(v1, h1, l1);
        g_w2h[j] = pack_bf2(h0, h1);
        g_w2l[j] = pack_bf2(l0, l1);
    }
    if (blockIdx.x == 0) {
        bool ok = true;
        for (int j = threadIdx.x; j < 4096; j += blockDim.x)
            if (ei[2 * j + 1] != 0) ok = false;
        int all = __syncthreads_and((int)ok);
        if (threadIdx.x == 0) g_is64 = all ? 1 : 0;
    }
}
__global__ void k_hist(const void* ei) {
    int e = blockIdx.x * blockDim.x + threadIdx.x;
    if (e < N_EDGES) atomicAdd(&g_deg[edst(ei, e)], 1);
}
__global__ void k_scan_block() {
    __shared__ int s[SCAN_B];
    int i = blockIdx.x * SCAN_B + threadIdx.x;
    int v = (i < N_NODES) ? g_deg[i] : 0;
    s[threadIdx.x] = v;
    __syncthreads();
    for (int off = 1; off < SCAN_B; off <<= 1) {
        int t = (threadIdx.x >= off) ? s[threadIdx.x - off] : 0;
        __syncthreads();
        s[threadIdx.x] += t;
        __syncthreads();
    }
    if (i < N_NODES) g_rowptr[i] = s[threadIdx.x] - v;
    if (threadIdx.x == SCAN_B - 1) g_part[blockIdx.x] = s[SCAN_B - 1];
}
__global__ void k_scan_add() {
    __shared__ int sp[256];
    int t = threadIdx.x;
    if (t < 256) sp[t] = (t < SCAN_NB) ? g_part[t] : 0;
    __syncthreads();
    for (int off = 1; off < 256; off <<= 1) {
        int v = (t < 256 && t >= off) ? sp[t - off] : 0;
        __syncthreads();
        if (t < 256) sp[t] += v;
        __syncthreads();
    }
    int offset = (blockIdx.x == 0) ? 0 : sp[blockIdx.x - 1];
    int i = blockIdx.x * SCAN_B + t;
    if (i < N_NODES) {
        int r = g_rowptr[i] + offset;
        g_rowptr[i] = r;
        g_fill[i] = r;
    }
    if (i == 0) g_rowptr[N_NODES] = N_EDGES;
}
__global__ void k_scatter(const void* ei) {
    int e = blockIdx.x * blockDim.x + threadIdx.x;
    if (e < N_EDGES) {
        int d = edst(ei, e);
        int p = atomicAdd(&g_fill[d], 1);
        g_col[p] = esrc(ei, e);
    }
}

// ---------------- fused: aggregate(fp16, MLP4) + GEMM1 + relu + GEMM2 -----
__global__ void __launch_bounds__(512) k_fused(const float* __restrict__ x,
                                               const float* __restrict__ b1) {
    extern __shared__ char dsm[];
    __nv_bfloat16* sAh = (__nv_bfloat16*)(dsm + SM_AH);
    __nv_bfloat16* sAl = (__nv_bfloat16*)(dsm + SM_AL);
    __nv_bfloat16* sW1h = (__nv_bfloat16*)(dsm + SM_W1H);
    __nv_bfloat16* sW1l = (__nv_bfloat16*)(dsm + SM_W1L);
    __nv_bfloat16* sW2h = (__nv_bfloat16*)(dsm + SM_W2H);
    __nv_bfloat16* sW2l = (__nv_bfloat16*)(dsm + SM_W2L);
    float* sB = (float*)(dsm + SM_BIAS);

    int tid = threadIdx.x, wid = tid >> 5, lane = tid & 31;
    int base = blockIdx.x * TILE_M;

    // ---- stage weights ----
    for (int i = tid; i < 128 * 16; i += 512) {
        int r = i >> 4, c8 = i & 15;
        *(uint4*)((char*)sW1h + r * (LDS_ROW * 2) + c8 * 16) = *(const uint4*)(g_w1h + r * 64 + c8 * 4);
        *(uint4*)((char*)sW1l + r * (LDS_ROW * 2) + c8 * 16) = *(const uint4*)(g_w1l + r * 64 + c8 * 4);
    }
    for (int i = tid; i < W2ROWS * 16; i += 512) {
        int r = i >> 4, c8 = i & 15;
        *(uint4*)((char*)sW2h + r * (LDS_ROW * 2) + c8 * 16) = *(const uint4*)(g_w2h + r * 64 + c8 * 4);
        *(uint4*)((char*)sW2l + r * (LDS_ROW * 2) + c8 * 16) = *(const uint4*)(g_w2l + r * 64 + c8 * 4);
    }
    if (tid < DHID) sB[tid] = b1[tid];

    // ---- gather-aggregate (fp16 half2/lane, 4 edges in flight) ----
    // warp w: rows w*8..w*8+7; lane covers col pair (2*lane, 2*lane+1)
#pragma unroll 1
    for (int i = 0; i < 8; i++) {
        int r = wid * 8 + i;
        int n = base + r;
        float a0 = 0.f, a1 = 0.f, b0 = 0.f, b1v = 0.f;
        float c0 = 0.f, c1 = 0.f, d0 = 0.f, d1 = 0.f;
        float s0v = 0.f, s1v = 0.f;
        float inv = 1.f;
        if (n < N_NODES) {
            int s0 = g_rowptr[n], s1 = g_rowptr[n + 1];
            int e = s0;
            for (; e + 3 < s1; e += 4) {
                uint32_t p0 = g_xh[(size_t)g_col[e] * 32 + lane];
                uint32_t p1 = g_xh[(size_t)g_col[e + 1] * 32 + lane];
                uint32_t p2 = g_xh[(size_t)g_col[e + 2] * 32 + lane];
                uint32_t p3 = g_xh[(size_t)g_col[e + 3] * 32 + lane];
                float2 f0 = __half22float2(*(__half2*)&p0);
                float2 f1 = __half22float2(*(__half2*)&p1);
                float2 f2 = __half22float2(*(__half2*)&p2);
                float2 f3 = __half22float2(*(__half2*)&p3);
                a0 += f0.x; a1 += f0.y;
                b0 += f1.x; b1v += f1.y;
                c0 += f2.x; c1 += f2.y;
                d0 += f3.x; d1 += f3.y;
            }
            for (; e < s1; e++) {
                uint32_t p0 = g_xh[(size_t)g_col[e] * 32 + lane];
                float2 f0 = __half22float2(*(__half2*)&p0);
                a0 += f0.x; a1 += f0.y;
            }
            a0 += b0 + c0 + d0;
            a1 += b1v + c1 + d1;
            inv = 1.f / (float)max(s1 - s0, 1);
            float2 sv = *(const float2*)&x[(size_t)n * DIN + 2 * lane];
            s0v = sv.x; s1v = sv.y;
        }
        a0 *= inv; a1 *= inv;
        __nv_bfloat16 h0, l0, h1, l1;
        split_bf16(a0, h0, l0); split_bf16(a1, h1, l1);
        *(uint32_t*)(sAh + r * LDS_ROW + 2 * lane) = pack_bf2(h0, h1);
        *(uint32_t*)(sAl + r * LDS_ROW + 2 * lane) = pack_bf2(l0, l1);
        split_bf16(s0v, h0, l0); split_bf16(s1v, h1, l1);
        *(uint32_t*)(sAh + r * LDS_ROW + 64 + 2 * lane) = pack_bf2(h0, h1);
        *(uint32_t*)(sAl + r * LDS_ROW + 64 + 2 * lane) = pack_bf2(l0, l1);
    }
    __syncthreads();

    // ---- GEMM1: 128x128, warp grid 4(M) x 4(N), warp tile 32x32 ----
    int Rb = (wid & 3) * 32;
    int Nb = (wid >> 2) * 32;
    int qr = lane >> 2;
    int qc = 2 * (lane & 3);

    float acc[2][4][4];
#pragma unroll
    for (int mt = 0; mt < 2; mt++)
#pragma unroll
        for (int nt = 0; nt < 4; nt++)
#pragma unroll
            for (int j = 0; j < 4; j++) acc[mt][nt][j] = 0.f;

    for (int ks = 0; ks < 8; ks++) {
        int kc = ks * 16 + qc;
        uint32_t ah[2][4], al[2][4];
#pragma unroll
        for (int mt = 0; mt < 2; mt++) {
            int r = Rb + mt * 16 + qr;
            ah[mt][0] = *(const uint32_t*)(sAh + r * LDS_ROW + kc);
            ah[mt][1] = *(const uint32_t*)(sAh + (r + 8) * LDS_ROW + kc);
            ah[mt][2] = *(const uint32_t*)(sAh + r * LDS_ROW + kc + 8);
            ah[mt][3] = *(const uint32_t*)(sAh + (r + 8) * LDS_ROW + kc + 8);
            al[mt][0] = *(const uint32_t*)(sAl + r * LDS_ROW + kc);
            al[mt][1] = *(const uint32_t*)(sAl + (r + 8) * LDS_ROW + kc);
            al[mt][2] = *(const uint32_t*)(sAl + r * LDS_ROW + kc + 8);
            al[mt][3] = *(const uint32_t*)(sAl + (r + 8) * LDS_ROW + kc + 8);
        }
#pragma unroll
        for (int nt = 0; nt < 4; nt++) {
            int nn = Nb + nt * 8 + qr;
            uint32_t bh0 = *(const uint32_t*)(sW1h + nn * LDS_ROW + kc);
            uint32_t bh1 = *(const uint32_t*)(sW1h + nn * LDS_ROW + kc + 8);
            uint32_t bl0 = *(const uint32_t*)(sW1l + nn * LDS_ROW + kc);
            uint32_t bl1 = *(const uint32_t*)(sW1l + nn * LDS_ROW + kc + 8);
#pragma unroll
            for (int mt = 0; mt < 2; mt++) {
                mma16816(acc[mt][nt], ah[mt], bh0, bh1);
                mma16816(acc[mt][nt], al[mt], bh0, bh1);
                mma16816(acc[mt][nt], ah[mt], bl0, bl1);
            }
        }
    }
    __syncthreads();  // done reading A; safe to overwrite with h1

    // ---- epilogue 1: bias + relu + resplit -> sAh/sAl (h1 tile) ----
#pragma unroll
    for (int mt = 0; mt < 2; mt++) {
#pragma unroll
        for (int nt = 0; nt < 4; nt++) {
            int c = Nb + nt * 8 + qc;
            float bv0 = sB[c], bv1 = sB[c + 1];
#pragma unroll
            for (int half = 0; half < 2; half++) {
                int r = Rb + mt * 16 + qr + half * 8;
                float v0 = acc[mt][nt][2 * half] + bv0;
                float v1 = acc[mt][nt][2 * half + 1] + bv1;
                v0 = v0 > 0.f ? v0 : 0.f;
                v1 = v1 > 0.f ? v1 : 0.f;
                __nv_bfloat16 h0, h1, l0, l1;
                split_bf16(v0, h0, l0);
                split_bf16(v1, h1, l1);
                *(uint32_t*)(sAh + r * LDS_ROW + c) = pack_bf2(h0, h1);
                *(uint32_t*)(sAl + r * LDS_ROW + c) = pack_bf2(l0, l1);
            }
        }
    }
    __syncthreads();

    // ---- GEMM2: 128x80, warp grid 8(M) x 2(N), warp tile 16x40 ----
    int Rb2 = (wid & 7) * 16;
    int Nb2 = (wid >> 3) * 40;

    float acc2[5][4];
#pragma unroll
    for (int nt = 0; nt < 5; nt++)
#pragma unroll
        for (int j = 0; j < 4; j++) acc2[nt][j] = 0.f;

    for (int ks = 0; ks < 8; ks++) {
        int kc = ks * 16 + qc;
        int r = Rb2 + qr;
        uint32_t ah[4], al[4];
        ah[0] = *(const uint32_t*)(sAh + r * LDS_ROW + kc);
        ah[1] = *(const uint32_t*)(sAh + (r + 8) * LDS_ROW + kc);
        ah[2] = *(const uint32_t*)(sAh + r * LDS_ROW + kc + 8);
        ah[3] = *(const uint32_t*)(sAh + (r + 8) * LDS_ROW + kc + 8);
        al[0] = *(const uint32_t*)(sAl + r * LDS_ROW + kc);
        al[1] = *(const uint32_t*)(sAl + (r + 8) * LDS_ROW + kc);
        al[2] = *(const uint32_t*)(sAl + r * LDS_ROW + kc + 8);
        al[3] = *(const uint32_t*)(sAl + (r + 8) * LDS_ROW + kc + 8);
#pragma unroll
        for (int nt = 0; nt < 5; nt++) {
            int nn = Nb2 + nt * 8 + qr;
            uint32_t bh0 = *(const uint32_t*)(sW2h + nn * LDS_ROW + kc);
            uint32_t bh1 = *(const uint32_t*)(sW2h + nn * LDS_ROW + kc + 8);
            uint32_t bl0 = *(const uint32_t*)(sW2l + nn * LDS_ROW + kc);
            uint32_t bl1 = *(const uint32_t*)(sW2l + nn * LDS_ROW + kc + 8);
            mma16816(acc2[nt], ah, bh0, bh1);
            mma16816(acc2[nt], al, bh0, bh1);
            mma16816(acc2[nt], ah, bl0, bl1);
        }
    }

    // ---- epilogue 2: write y2l (half2, stride 24 words) / y2r (fp32) ----
#pragma unroll
    for (int nt = 0; nt < 5; nt++) {
        int c = Nb2 + nt * 8 + qc;  // 0..78 even
        int n0 = base + Rb2 + qr;
        int n1 = n0 + 8;
        if (c < DOUT) {
            __half2 h0 = __floats2half2_rn(acc2[nt][0], acc2[nt][1]);
            __half2 h1 = __floats2half2_rn(acc2[nt][2], acc2[nt][3]);
            if (n0 < N_NODES) g_y2l[(size_t)n0 * Y2L_W32 + (c >> 1)] = *(uint32_t*)&h0;
            if (n1 < N_NODES) g_y2l[(size_t)n1 * Y2L_W32 + (c >> 1)] = *(uint32_t*)&h1;
        } else {
            int cc = c - DOUT;
            if (n0 < N_NODES)
                *(float2*)&g_y2r[(size_t)n0 * DOUT + cc] = make_float2(acc2[nt][0], acc2[nt][1]);
            if (n1 < N_NODES)
                *(float2*)&g_y2r[(size_t)n1 * DOUT + cc] = make_float2(acc2[nt][2], acc2[nt][3]);
        }
    }
}

// ---------------- final: out = log_softmax(mean-agg(y2l) + b2 + y2r) ------
// one warp/node; lane l<20 owns output pair (2l, 2l+1); y2l gathered as half2
__global__ void k_out(const float* __restrict__ b2, float* __restrict__ out) {
    int warp = (blockIdx.x * blockDim.x + threadIdx.x) >> 5;
    int lane = threadIdx.x & 31;
    if (warp >= N_NODES) return;
    float a0 = 0.f, a1 = 0.f, b0 = 0.f, b1v = 0.f;
    float c0 = 0.f, c1 = 0.f, d0 = 0.f, d1 = 0.f;
    int s0 = g_rowptr[warp], s1 = g_rowptr[warp + 1];
    int e = s0;
    // lanes >= 20 read pad region (array over-allocated); values unused
    int ln = (lane < 20) ? lane : 0;
    for (; e + 3 < s1; e += 4) {
        uint32_t p0 = g_y2l[(size_t)g_col[e] * Y2L_W32 + ln];
        uint32_t p1 = g_y2l[(size_t)g_col[e + 1] * Y2L_W32 + ln];
        uint32_t p2 = g_y2l[(size_t)g_col[e + 2] * Y2L_W32 + ln];
        uint32_t p3 = g_y2l[(size_t)g_col[e + 3] * Y2L_W32 + ln];
        float2 f0 = __half22float2(*(__half2*)&p0);
        float2 f1 = __half22float2(*(__half2*)&p1);
        float2 f2 = __half22float2(*(__half2*)&p2);
        float2 f3 = __half22float2(*(__half2*)&p3);
        a0 += f0.x; a1 += f0.y;
        b0 += f1.x; b1v += f1.y;
        c0 += f2.x; c1 += f2.y;
        d0 += f3.x; d1 += f3.y;
    }
    for (; e < s1; e++) {
        uint32_t p0 = g_y2l[(size_t)g_col[e] * Y2L_W32 + ln];
        float2 f0 = __half22float2(*(__half2*)&p0);
        a0 += f0.x; a1 += f0.y;
    }
    a0 += b0 + c0 + d0;
    a1 += b1v + c1 + d1;
    float inv = 1.f / (float)max(s1 - s0, 1);
    size_t nb = (size_t)warp * DOUT;
    float v0 = -INFINITY, v1 = -INFINITY;
    if (lane < 20) {
        v0 = a0 * inv + b2[2 * lane] + g_y2r[nb + 2 * lane];
        v1 = a1 * inv + b2[2 * lane + 1] + g_y2r[nb + 2 * lane + 1];
    }
    float m = fmaxf(v0, v1);
    for (int off = 16; off; off >>= 1)
        m = fmaxf(m, __shfl_xor_sync(0xffffffffu, m, off));
    float s = (lane < 20) ? (expf(v0 - m) + expf(v1 - m)) : 0.f;
    for (int off = 16; off; off >>= 1)
        s += __shfl_xor_sync(0xffffffffu, s, off);
    float lse = m + logf(s);
    if (lane < 20)
        *(float2*)&out[nb + 2 * lane] = make_float2(v0 - lse, v1 - lse);
}

// ---------------- launch --------------------------------------------------
extern "C" void kernel_launch(void* const* d_in, const int* in_sizes, int n_in,
                              void* d_out, int out_size) {
    const float* x = (const float*)d_in[0];
    const void* ei = d_in[1];
    const float* W1l = (const float*)d_in[2];
    const float* b1 = (const float*)d_in[3];
    const float* W1r = (const float*)d_in[4];
    const float* W2l = (const float*)d_in[5];
    const float* b2 = (const float*)d_in[6];
    const float* W2r = (const float*)d_in[7];
    float* out = (float*)d_out;

    cudaFuncSetAttribute(k_fused, cudaFuncAttributeMaxDynamicSharedMemorySize,
                         SM_TOTAL);

    k_init<<<(N_NODES * 32 + 255) / 256, 256>>>((const int*)ei, x, W1l, W1r, W2l, W2r);
    k_hist<<<(N_EDGES + 255) / 256, 256>>>(ei);
    k_scan_block<<<SCAN_NB, SCAN_B>>>();
    k_scan_add<<<SCAN_NB, SCAN_B>>>();
    k_scatter<<<(N_EDGES + 255) / 256, 256>>>(ei);

    k_fused<<<N_TILES, 512, SM_TOTAL>>>(x, b1);
    k_out<<<(N_NODES * 32 + 255) / 256, 256>>>(b2, out);
}

// round 10
// speedup vs baseline: 1.1258x; 1.1258x over previous
#include <cuda_runtime.h>
#include <cuda_bf16.h>
#include <cuda_fp16.h>
#include <math.h>
#include <stdint.h>

#define N_NODES 100000
#define N_EDGES 1600000
#define DIN 64
#define DHID 128
#define DOUT 40
#define Y2L_W32 24  // y2l row stride in uint32 (48 halves = 96B)
#define SCAN_B 512
#define SCAN_NB ((N_NODES + SCAN_B - 1) / SCAN_B)
#define TILE_M 128
#define N_TILES ((N_NODES + TILE_M - 1) / TILE_M)  // 782
#define W2ROWS 80
#define LDS_ROW 136  // bf16 elems per SMEM row (128 + 8 pad) -> conflict-free frags

// SMEM byte offsets for MMA kernel
#define SM_AH 0
#define SM_AL 34816
#define SM_W1H 69632
#define SM_W1L 104448
#define SM_W2H 139264
#define SM_W2L 161024
#define SM_BIAS 182784
#define SM_TOTAL 183424

// ---------------- device scratch ----------------
__device__ int g_is64;
__device__ int g_deg[N_NODES];
__device__ int g_rowptr[N_NODES + 1];
__device__ int g_fill[N_NODES];
__device__ int g_col[N_EDGES];
__device__ int g_part[256];
__device__ uint32_t g_xh[(size_t)N_NODES * 32];  // x as half2 pairs [node][32]
__device__ uint32_t g_ah[(size_t)N_NODES * 64];  // A hi: bf16x2 [node][64] (=128 cols)
__device__ uint32_t g_al[(size_t)N_NODES * 64];  // A lo
__device__ uint32_t g_w1h[DHID * 64], g_w1l[DHID * 64];      // [128 out][128 k] bf16x2
__device__ uint32_t g_w2h[W2ROWS * 64], g_w2l[W2ROWS * 64];  // [80 out][128 k]
__device__ uint32_t g_y2l[(size_t)N_NODES * Y2L_W32 + 32];   // half2, padded tail
__device__ float g_y2r[(size_t)N_NODES * DOUT];

// ---------------- helpers ----------------
__device__ __forceinline__ void mma16816(float* c, const uint32_t* a,
                                         uint32_t b0, uint32_t b1) {
    asm volatile(
        "mma.sync.aligned.m16n8k16.row.col.f32.bf16.bf16.f32 "
        "{%0,%1,%2,%3}, {%4,%5,%6,%7}, {%8,%9}, {%0,%1,%2,%3};"
        : "+f"(c[0]), "+f"(c[1]), "+f"(c[2]), "+f"(c[3])
        : "r"(a[0]), "r"(a[1]), "r"(a[2]), "r"(a[3]), "r"(b0), "r"(b1));
}
__device__ __forceinline__ void split_bf16(float v, __nv_bfloat16& h, __nv_bfloat16& l) {
    h = __float2bfloat16_rn(v);
    l = __float2bfloat16_rn(v - __bfloat162float(h));
}
__device__ __forceinline__ uint32_t pack_bf2(__nv_bfloat16 a, __nv_bfloat16 b) {
    __nv_bfloat162 p = __nv_bfloat162(a, b);
    return *(uint32_t*)&p;
}

// ---------------- edge index access (int64 or int32, runtime-detected) ----
__device__ __forceinline__ int edst(const void* ei, int e) {
    return g_is64 ? (int)((const long long*)ei)[(size_t)N_EDGES + e]
                  : ((const int*)ei)[(size_t)N_EDGES + e];
}
__device__ __forceinline__ int esrc(const void* ei, int e) {
    return g_is64 ? (int)((const long long*)ei)[e] : ((const int*)ei)[e];
}

// init degrees + dtype detect + weight split + x->fp16 conversion
__global__ void k_init(const int* ei, const float* __restrict__ x,
                       const float* __restrict__ W1l, const float* __restrict__ W1r,
                       const float* __restrict__ W2l, const float* __restrict__ W2r) {
    int i = blockIdx.x * blockDim.x + threadIdx.x;
    if (i < N_NODES) g_deg[i] = 0;
    if (i < N_NODES * 32) {
        int n = i >> 5, q = i & 31;
        float2 v = *(const float2*)&x[(size_t)n * DIN + 2 * q];
        __half2 h = __floats2half2_rn(v.x, v.y);
        g_xh[(size_t)n * 32 + q] = *(uint32_t*)&h;
    }
    int tot1 = DHID * 64;
    if (i < tot1) {
        int o = i >> 6, c = 2 * (i & 63);
        float v0 = (c < 64) ? W1l[o * 64 + c] : W1r[o * 64 + c - 64];
        float v1 = (c < 64) ? W1l[o * 64 + c + 1] : W1r[o * 64 + c - 63];
        __nv_bfloat16 h0, h1, l0, l1;
        split_bf16(v0, h0, l0); split_bf16(v1, h1, l1);
        g_w1h[i] = pack_bf2(h0, h1);
        g_w1l[i] = pack_bf2(l0, l1);
    } else if (i < tot1 + W2ROWS * 64) {
        int j = i - tot1;
        int o = j >> 6, c = 2 * (j & 63);
        float v0 = (o < DOUT) ? W2l[o * DHID + c] : W2r[(o - DOUT) * DHID + c];
        float v1 = (o < DOUT) ? W2l[o * DHID + c + 1] : W2r[(o - DOUT) * DHID + c + 1];
        __nv_bfloat16 h0, h1, l0, l1;
        split_bf16(v0, h0, l0); split_bf16(v1, h1, l1);
        g_w2h[j] = pack_bf2(h0, h1);
        g_w2l[j] = pack_bf2(l0, l1);
    }
    if (blockIdx.x == 0) {
        bool ok = true;
        for (int j = threadIdx.x; j < 4096; j += blockDim.x)
            if (ei[2 * j + 1] != 0) ok = false;
        int all = __syncthreads_and((int)ok);
        if (threadIdx.x == 0) g_is64 = all ? 1 : 0;
    }
}
__global__ void k_hist(const void* ei) {
    int e = blockIdx.x * blockDim.x + threadIdx.x;
    if (e < N_EDGES) atomicAdd(&g_deg[edst(ei, e)], 1);
}
__global__ void k_scan_block() {
    __shared__ int s[SCAN_B];
    int i = blockIdx.x * SCAN_B + threadIdx.x;
    int v = (i < N_NODES) ? g_deg[i] : 0;
    s[threadIdx.x] = v;
    __syncthreads();
    for (int off = 1; off < SCAN_B; off <<= 1) {
        int t = (threadIdx.x >= off) ? s[threadIdx.x - off] : 0;
        __syncthreads();
        s[threadIdx.x] += t;
        __syncthreads();
    }
    if (i < N_NODES) g_rowptr[i] = s[threadIdx.x] - v;
    if (threadIdx.x == SCAN_B - 1) g_part[blockIdx.x] = s[SCAN_B - 1];
}
__global__ void k_scan_add() {
    __shared__ int sp[256];
    int t = threadIdx.x;
    if (t < 256) sp[t] = (t < SCAN_NB) ? g_part[t] : 0;
    __syncthreads();
    for (int off = 1; off < 256; off <<= 1) {
        int v = (t < 256 && t >= off) ? sp[t - off] : 0;
        __syncthreads();
        if (t < 256) sp[t] += v;
        __syncthreads();
    }
    int offset = (blockIdx.x == 0) ? 0 : sp[blockIdx.x - 1];
    int i = blockIdx.x * SCAN_B + t;
    if (i < N_NODES) {
        int r = g_rowptr[i] + offset;
        g_rowptr[i] = r;
        g_fill[i] = r;
    }
    if (i == 0) g_rowptr[N_NODES] = N_EDGES;
}
__global__ void k_scatter(const void* ei) {
    int e = blockIdx.x * blockDim.x + threadIdx.x;
    if (e < N_EDGES) {
        int d = edst(ei, e);
        int p = atomicAdd(&g_fill[d], 1);
        g_col[p] = esrc(ei, e);
    }
}

// ---------------- k_agg: warp-per-node gather (HIGH occupancy) -----------
// Lane covers col pair (2l, 2l+1). fp16 source, 4 edges in flight.
// Emits split-bf16 A row: [agg(0..63) | self(64..127)] as u32 pairs.
__global__ void __launch_bounds__(256) k_agg(const float* __restrict__ x) {
    int warp = (blockIdx.x * blockDim.x + threadIdx.x) >> 5;
    int lane = threadIdx.x & 31;
    if (warp >= N_NODES) return;
    float a0 = 0.f, a1 = 0.f, b0 = 0.f, b1v = 0.f;
    float c0 = 0.f, c1 = 0.f, d0 = 0.f, d1 = 0.f;
    int s0 = g_rowptr[warp], s1 = g_rowptr[warp + 1];
    int e = s0;
    for (; e + 3 < s1; e += 4) {
        uint32_t p0 = g_xh[g_col[e] * 32 + lane];
        uint32_t p1 = g_xh[g_col[e + 1] * 32 + lane];
        uint32_t p2 = g_xh[g_col[e + 2] * 32 + lane];
        uint32_t p3 = g_xh[g_col[e + 3] * 32 + lane];
        float2 f0 = __half22float2(*(__half2*)&p0);
        float2 f1 = __half22float2(*(__half2*)&p1);
        float2 f2 = __half22float2(*(__half2*)&p2);
        float2 f3 = __half22float2(*(__half2*)&p3);
        a0 += f0.x; a1 += f0.y;
        b0 += f1.x; b1v += f1.y;
        c0 += f2.x; c1 += f2.y;
        d0 += f3.x; d1 += f3.y;
    }
    for (; e < s1; e++) {
        uint32_t p0 = g_xh[g_col[e] * 32 + lane];
        float2 f0 = __half22float2(*(__half2*)&p0);
        a0 += f0.x; a1 += f0.y;
    }
    a0 += b0 + c0 + d0;
    a1 += b1v + c1 + d1;
    float inv = 1.f / (float)max(s1 - s0, 1);
    a0 *= inv; a1 *= inv;
    __nv_bfloat16 h0, l0, h1, l1;
    split_bf16(a0, h0, l0); split_bf16(a1, h1, l1);
    g_ah[(size_t)warp * 64 + lane] = pack_bf2(h0, h1);
    g_al[(size_t)warp * 64 + lane] = pack_bf2(l0, l1);
    float2 sv = *(const float2*)&x[(size_t)warp * DIN + 2 * lane];
    split_bf16(sv.x, h0, l0); split_bf16(sv.y, h1, l1);
    g_ah[(size_t)warp * 64 + 32 + lane] = pack_bf2(h0, h1);
    g_al[(size_t)warp * 64 + 32 + lane] = pack_bf2(l0, l1);
}

// ---------------- k_mma: A-tile load + GEMM1 + relu + GEMM2 ---------------
__global__ void __launch_bounds__(512) k_mma(const float* __restrict__ b1) {
    extern __shared__ char dsm[];
    __nv_bfloat16* sAh = (__nv_bfloat16*)(dsm + SM_AH);
    __nv_bfloat16* sAl = (__nv_bfloat16*)(dsm + SM_AL);
    __nv_bfloat16* sW1h = (__nv_bfloat16*)(dsm + SM_W1H);
    __nv_bfloat16* sW1l = (__nv_bfloat16*)(dsm + SM_W1L);
    __nv_bfloat16* sW2h = (__nv_bfloat16*)(dsm + SM_W2H);
    __nv_bfloat16* sW2l = (__nv_bfloat16*)(dsm + SM_W2L);
    float* sB = (float*)(dsm + SM_BIAS);

    int tid = threadIdx.x, wid = tid >> 5, lane = tid & 31;
    int base = blockIdx.x * TILE_M;

    // ---- stage A tile (coalesced from k_agg output) + weights ----
    for (int i = tid; i < 128 * 16; i += 512) {
        int r = i >> 4, c8 = i & 15;
        int n = base + r;
        uint4 vh = make_uint4(0, 0, 0, 0), vl = make_uint4(0, 0, 0, 0);
        if (n < N_NODES) {
            vh = *(const uint4*)(g_ah + (size_t)n * 64 + c8 * 4);
            vl = *(const uint4*)(g_al + (size_t)n * 64 + c8 * 4);
        }
        *(uint4*)((char*)sAh + r * (LDS_ROW * 2) + c8 * 16) = vh;
        *(uint4*)((char*)sAl + r * (LDS_ROW * 2) + c8 * 16) = vl;
    }
    for (int i = tid; i < 128 * 16; i += 512) {
        int r = i >> 4, c8 = i & 15;
        *(uint4*)((char*)sW1h + r * (LDS_ROW * 2) + c8 * 16) = *(const uint4*)(g_w1h + r * 64 + c8 * 4);
        *(uint4*)((char*)sW1l + r * (LDS_ROW * 2) + c8 * 16) = *(const uint4*)(g_w1l + r * 64 + c8 * 4);
    }
    for (int i = tid; i < W2ROWS * 16; i += 512) {
        int r = i >> 4, c8 = i & 15;
        *(uint4*)((char*)sW2h + r * (LDS_ROW * 2) + c8 * 16) = *(const uint4*)(g_w2h + r * 64 + c8 * 4);
        *(uint4*)((char*)sW2l + r * (LDS_ROW * 2) + c8 * 16) = *(const uint4*)(g_w2l + r * 64 + c8 * 4);
    }
    if (tid < DHID) sB[tid] = b1[tid];
    __syncthreads();

    // ---- GEMM1: 128x128, warp grid 4(M) x 4(N), warp tile 32x32 ----
    int Rb = (wid & 3) * 32;
    int Nb = (wid >> 2) * 32;
    int qr = lane >> 2;
    int qc = 2 * (lane & 3);

    float acc[2][4][4];
#pragma unroll
    for (int mt = 0; mt < 2; mt++)
#pragma unroll
        for (int nt = 0; nt < 4; nt++)
#pragma unroll
            for (int j = 0; j < 4; j++) acc[mt][nt][j] = 0.f;

    for (int ks = 0; ks < 8; ks++) {
        int kc = ks * 16 + qc;
        uint32_t ah[2][4], al[2][4];
#pragma unroll
        for (int mt = 0; mt < 2; mt++) {
            int r = Rb + mt * 16 + qr;
            ah[mt][0] = *(const uint32_t*)(sAh + r * LDS_ROW + kc);
            ah[mt][1] = *(const uint32_t*)(sAh + (r + 8) * LDS_ROW + kc);
            ah[mt][2] = *(const uint32_t*)(sAh + r * LDS_ROW + kc + 8);
            ah[mt][3] = *(const uint32_t*)(sAh + (r + 8) * LDS_ROW + kc + 8);
            al[mt][0] = *(const uint32_t*)(sAl + r * LDS_ROW + kc);
            al[mt][1] = *(const uint32_t*)(sAl + (r + 8) * LDS_ROW + kc);
            al[mt][2] = *(const uint32_t*)(sAl + r * LDS_ROW + kc + 8);
            al[mt][3] = *(const uint32_t*)(sAl + (r + 8) * LDS_ROW + kc + 8);
        }
#pragma unroll
        for (int nt = 0; nt < 4; nt++) {
            int nn = Nb + nt * 8 + qr;
            uint32_t bh0 = *(const uint32_t*)(sW1h + nn * LDS_ROW + kc);
            uint32_t bh1 = *(const uint32_t*)(sW1h + nn * LDS_ROW + kc + 8);
            uint32_t bl0 = *(const uint32_t*)(sW1l + nn * LDS_ROW + kc);
            uint32_t bl1 = *(const uint32_t*)(sW1l + nn * LDS_ROW + kc + 8);
#pragma unroll
            for (int mt = 0; mt < 2; mt++) {
                mma16816(acc[mt][nt], ah[mt], bh0, bh1);
                mma16816(acc[mt][nt], al[mt], bh0, bh1);
                mma16816(acc[mt][nt], ah[mt], bl0, bl1);
            }
        }
    }
    __syncthreads();  // done reading A; safe to overwrite with h1

    // ---- epilogue 1: bias + relu + resplit -> sAh/sAl (h1 tile) ----
#pragma unroll
    for (int mt = 0; mt < 2; mt++) {
#pragma unroll
        for (int nt = 0; nt < 4; nt++) {
            int c = Nb + nt * 8 + qc;
            float bv0 = sB[c], bv1 = sB[c + 1];
#pragma unroll
            for (int half = 0; half < 2; half++) {
                int r = Rb + mt * 16 + qr + half * 8;
                float v0 = acc[mt][nt][2 * half] + bv0;
                float v1 = acc[mt][nt][2 * half + 1] + bv1;
                v0 = v0 > 0.f ? v0 : 0.f;
                v1 = v1 > 0.f ? v1 : 0.f;
                __nv_bfloat16 h0, h1, l0, l1;
                split_bf16(v0, h0, l0);
                split_bf16(v1, h1, l1);
                *(uint32_t*)(sAh + r * LDS_ROW + c) = pack_bf2(h0, h1);
                *(uint32_t*)(sAl + r * LDS_ROW + c) = pack_bf2(l0, l1);
            }
        }
    }
    __syncthreads();

    // ---- GEMM2: 128x80, warp grid 8(M) x 2(N), warp tile 16x40 ----
    int Rb2 = (wid & 7) * 16;
    int Nb2 = (wid >> 3) * 40;

    float acc2[5][4];
#pragma unroll
    for (int nt = 0; nt < 5; nt++)
#pragma unroll
        for (int j = 0; j < 4; j++) acc2[nt][j] = 0.f;

    for (int ks = 0; ks < 8; ks++) {
        int kc = ks * 16 + qc;
        int r = Rb2 + qr;
        uint32_t ah[4], al[4];
        ah[0] = *(const uint32_t*)(sAh + r * LDS_ROW + kc);
        ah[1] = *(const uint32_t*)(sAh + (r + 8) * LDS_ROW + kc);
        ah[2] = *(const uint32_t*)(sAh + r * LDS_ROW + kc + 8);
        ah[3] = *(const uint32_t*)(sAh + (r + 8) * LDS_ROW + kc + 8);
        al[0] = *(const uint32_t*)(sAl + r * LDS_ROW + kc);
        al[1] = *(const uint32_t*)(sAl + (r + 8) * LDS_ROW + kc);
        al[2] = *(const uint32_t*)(sAl + r * LDS_ROW + kc + 8);
        al[3] = *(const uint32_t*)(sAl + (r + 8) * LDS_ROW + kc + 8);
#pragma unroll
        for (int nt = 0; nt < 5; nt++) {
            int nn = Nb2 + nt * 8 + qr;
            uint32_t bh0 = *(const uint32_t*)(sW2h + nn * LDS_ROW + kc);
            uint32_t bh1 = *(const uint32_t*)(sW2h + nn * LDS_ROW + kc + 8);
            uint32_t bl0 = *(const uint32_t*)(sW2l + nn * LDS_ROW + kc);
            uint32_t bl1 = *(const uint32_t*)(sW2l + nn * LDS_ROW + kc + 8);
            mma16816(acc2[nt], ah, bh0, bh1);
            mma16816(acc2[nt], al, bh0, bh1);
            mma16816(acc2[nt], ah, bl0, bl1);
        }
    }

    // ---- epilogue 2: write y2l (half2, stride 24 words) / y2r (fp32) ----
#pragma unroll
    for (int nt = 0; nt < 5; nt++) {
        int c = Nb2 + nt * 8 + qc;  // 0..78 even
        int n0 = base + Rb2 + qr;
        int n1 = n0 + 8;
        if (c < DOUT) {
            __half2 h0 = __floats2half2_rn(acc2[nt][0], acc2[nt][1]);
            __half2 h1 = __floats2half2_rn(acc2[nt][2], acc2[nt][3]);
            if (n0 < N_NODES) g_y2l[(size_t)n0 * Y2L_W32 + (c >> 1)] = *(uint32_t*)&h0;
            if (n1 < N_NODES) g_y2l[(size_t)n1 * Y2L_W32 + (c >> 1)] = *(uint32_t*)&h1;
        } else {
            int cc = c - DOUT;
            if (n0 < N_NODES)
                *(float2*)&g_y2r[(size_t)n0 * DOUT + cc] = make_float2(acc2[nt][0], acc2[nt][1]);
            if (n1 < N_NODES)
                *(float2*)&g_y2r[(size_t)n1 * DOUT + cc] = make_float2(acc2[nt][2], acc2[nt][3]);
        }
    }
}

// ---------------- final: out = log_softmax(mean-agg(y2l) + b2 + y2r) ------
// one warp/node; lane l<20 owns output pair (2l, 2l+1); y2l gathered as half2
__global__ void __launch_bounds__(256) k_out(const float* __restrict__ b2,
                                             float* __restrict__ out) {
    int warp = (blockIdx.x * blockDim.x + threadIdx.x) >> 5;
    int lane = threadIdx.x & 31;
    if (warp >= N_NODES) return;
    float a0 = 0.f, a1 = 0.f, b0 = 0.f, b1v = 0.f;
    float c0 = 0.f, c1 = 0.f, d0 = 0.f, d1 = 0.f;
    int s0 = g_rowptr[warp], s1 = g_rowptr[warp + 1];
    int e = s0;
    int ln = (lane < 20) ? lane : 0;
    for (; e + 3 < s1; e += 4) {
        uint32_t p0 = g_y2l[(size_t)g_col[e] * Y2L_W32 + ln];
        uint32_t p1 = g_y2l[(size_t)g_col[e + 1] * Y2L_W32 + ln];
        uint32_t p2 = g_y2l[(size_t)g_col[e + 2] * Y2L_W32 + ln];
        uint32_t p3 = g_y2l[(size_t)g_col[e + 3] * Y2L_W32 + ln];
        float2 f0 = __half22float2(*(__half2*)&p0);
        float2 f1 = __half22float2(*(__half2*)&p1);
        float2 f2 = __half22float2(*(__half2*)&p2);
        float2 f3 = __half22float2(*(__half2*)&p3);
        a0 += f0.x; a1 += f0.y;
        b0 += f1.x; b1v += f1.y;
        c0 += f2.x; c1 += f2.y;
        d0 += f3.x; d1 += f3.y;
    }
    for (; e < s1; e++) {
        uint32_t p0 = g_y2l[(size_t)g_col[e] * Y2L_W32 + ln];
        float2 f0 = __half22float2(*(__half2*)&p0);
        a0 += f0.x; a1 += f0.y;
    }
    a0 += b0 + c0 + d0;
    a1 += b1v + c1 + d1;
    float inv = 1.f / (float)max(s1 - s0, 1);
    size_t nb = (size_t)warp * DOUT;
    float v0 = -INFINITY, v1 = -INFINITY;
    if (lane < 20) {
        v0 = a0 * inv + b2[2 * lane] + g_y2r[nb + 2 * lane];
        v1 = a1 * inv + b2[2 * lane + 1] + g_y2r[nb + 2 * lane + 1];
    }
    float m = fmaxf(v0, v1);
    for (int off = 16; off; off >>= 1)
        m = fmaxf(m, __shfl_xor_sync(0xffffffffu, m, off));
    float s = (lane < 20) ? (expf(v0 - m) + expf(v1 - m)) : 0.f;
    for (int off = 16; off; off >>= 1)
        s += __shfl_xor_sync(0xffffffffu, s, off);
    float lse = m + logf(s);
    if (lane < 20)
        *(float2*)&out[nb + 2 * lane] = make_float2(v0 - lse, v1 - lse);
}

// ---------------- launch --------------------------------------------------
extern "C" void kernel_launch(void* const* d_in, const int* in_sizes, int n_in,
                              void* d_out, int out_size) {
    const float* x = (const float*)d_in[0];
    const void* ei = d_in[1];
    const float* W1l = (const float*)d_in[2];
    const float* b1 = (const float*)d_in[3];
    const float* W1r = (const float*)d_in[4];
    const float* W2l = (const float*)d_in[5];
    const float* b2 = (const float*)d_in[6];
    const float* W2r = (const float*)d_in[7];
    float* out = (float*)d_out;

    cudaFuncSetAttribute(k_mma, cudaFuncAttributeMaxDynamicSharedMemorySize,
                         SM_TOTAL);

    k_init<<<(N_NODES * 32 + 255) / 256, 256>>>((const int*)ei, x, W1l, W1r, W2l, W2r);
    k_hist<<<(N_EDGES + 255) / 256, 256>>>(ei);
    k_scan_block<<<SCAN_NB, SCAN_B>>>();
    k_scan_add<<<SCAN_NB, SCAN_B>>>();
    k_scatter<<<(N_EDGES + 255) / 256, 256>>>(ei);

    k_agg<<<(N_NODES * 32 + 255) / 256, 256>>>(x);
    k_mma<<<N_TILES, 512, SM_TOTAL>>>(b1);
    k_out<<<(N_NODES * 32 + 255) / 256, 256>>>(b2, out);
}

// round 11
// speedup vs baseline: 1.1801x; 1.0483x over previous
#include <cuda_runtime.h>
#include <cuda_bf16.h>
#include <cuda_fp16.h>
#include <math.h>
#include <stdint.h>

#define N_NODES 100000
#define N_EDGES 1600000
#define DIN 64
#define DHID 128
#define DOUT 40
#define Y2L_W32 24  // y2l row stride in uint32 (48 halves = 96B)
#define SCAN_B 512
#define SCAN_NB ((N_NODES + SCAN_B - 1) / SCAN_B)
#define TILE_M 128
#define N_TILES ((N_NODES + TILE_M - 1) / TILE_M)  // 782
#define W2ROWS 80
#define LDS_ROW 136  // bf16 elems per SMEM row (128 + 8 pad) -> conflict-free frags
#define MMA_GRID 148 // persistent CTAs

// SMEM byte offsets for MMA kernel
#define SM_AH 0
#define SM_AL 34816
#define SM_W1H 69632
#define SM_W1L 104448
#define SM_W2H 139264
#define SM_W2L 161024
#define SM_BIAS 182784
#define SM_TOTAL 183424

// ---------------- device scratch ----------------
__device__ int g_is64;
__device__ int g_deg[N_NODES];
__device__ int g_rowptr[N_NODES + 1];
__device__ int g_fill[N_NODES];
__device__ int g_col[N_EDGES];
__device__ int g_part[256];
__device__ uint32_t g_xh[(size_t)N_NODES * 32];  // x as half2 pairs [node][32]
__device__ uint32_t g_ah[(size_t)N_NODES * 64];  // A hi: bf16x2 [node][64] (=128 cols)
__device__ uint32_t g_al[(size_t)N_NODES * 64];  // A lo
__device__ uint32_t g_w1h[DHID * 64], g_w1l[DHID * 64];      // [128 out][128 k] bf16x2
__device__ uint32_t g_w2h[W2ROWS * 64], g_w2l[W2ROWS * 64];  // [80 out][128 k]
__device__ uint32_t g_y2l[(size_t)N_NODES * Y2L_W32 + 32];   // half2, padded tail
__device__ float g_y2r[(size_t)N_NODES * DOUT];

// ---------------- helpers ----------------
__device__ __forceinline__ void mma16816(float* c, const uint32_t* a,
                                         uint32_t b0, uint32_t b1) {
    asm volatile(
        "mma.sync.aligned.m16n8k16.row.col.f32.bf16.bf16.f32 "
        "{%0,%1,%2,%3}, {%4,%5,%6,%7}, {%8,%9}, {%0,%1,%2,%3};"
        : "+f"(c[0]), "+f"(c[1]), "+f"(c[2]), "+f"(c[3])
        : "r"(a[0]), "r"(a[1]), "r"(a[2]), "r"(a[3]), "r"(b0), "r"(b1));
}
__device__ __forceinline__ void split_bf16(float v, __nv_bfloat16& h, __nv_bfloat16& l) {
    h = __float2bfloat16_rn(v);
    l = __float2bfloat16_rn(v - __bfloat162float(h));
}
__device__ __forceinline__ uint32_t pack_bf2(__nv_bfloat16 a, __nv_bfloat16 b) {
    __nv_bfloat162 p = __nv_bfloat162(a, b);
    return *(uint32_t*)&p;
}

// ---------------- edge index access (int64 or int32, runtime-detected) ----
__device__ __forceinline__ int edst(const void* ei, int e) {
    return g_is64 ? (int)((const long long*)ei)[(size_t)N_EDGES + e]
                  : ((const int*)ei)[(size_t)N_EDGES + e];
}
__device__ __forceinline__ int esrc(const void* ei, int e) {
    return g_is64 ? (int)((const long long*)ei)[e] : ((const int*)ei)[e];
}

// init degrees + dtype detect + weight split + x->fp16 conversion
__global__ void k_init(const int* ei, const float* __restrict__ x,
                       const float* __restrict__ W1l, const float* __restrict__ W1r,
                       const float* __restrict__ W2l, const float* __restrict__ W2r) {
    int i = blockIdx.x * blockDim.x + threadIdx.x;
    if (i < N_NODES) g_deg[i] = 0;
    if (i < N_NODES * 32) {
        int n = i >> 5, q = i & 31;
        float2 v = *(const float2*)&x[(size_t)n * DIN + 2 * q];
        __half2 h = __floats2half2_rn(v.x, v.y);
        g_xh[(size_t)n * 32 + q] = *(uint32_t*)&h;
    }
    int tot1 = DHID * 64;
    if (i < tot1) {
        int o = i >> 6, c = 2 * (i & 63);
        float v0 = (c < 64) ? W1l[o * 64 + c] : W1r[o * 64 + c - 64];
        float v1 = (c < 64) ? W1l[o * 64 + c + 1] : W1r[o * 64 + c - 63];
        __nv_bfloat16 h0, h1, l0, l1;
        split_bf16(v0, h0, l0); split_bf16(v1, h1, l1);
        g_w1h[i] = pack_bf2(h0, h1);
        g_w1l[i] = pack_bf2(l0, l1);
    } else if (i < tot1 + W2ROWS * 64) {
        int j = i - tot1;
        int o = j >> 6, c = 2 * (j & 63);
        float v0 = (o < DOUT) ? W2l[o * DHID + c] : W2r[(o - DOUT) * DHID + c];
        float v1 = (o < DOUT) ? W2l[o * DHID + c + 1] : W2r[(o - DOUT) * DHID + c + 1];
        __nv_bfloat16 h0, h1, l0, l1;
        split_bf16(v0, h0, l0); split_bf16(v1, h1, l1);
        g_w2h[j] = pack_bf2(h0, h1);
        g_w2l[j] = pack_bf2(l0, l1);
    }
    if (blockIdx.x == 0) {
        bool ok = true;
        for (int j = threadIdx.x; j < 4096; j += blockDim.x)
            if (ei[2 * j + 1] != 0) ok = false;
        int all = __syncthreads_and((int)ok);
        if (threadIdx.x == 0) g_is64 = all ? 1 : 0;
    }
}
__global__ void k_hist(const void* ei) {
    int e = blockIdx.x * blockDim.x + threadIdx.x;
    if (e < N_EDGES) atomicAdd(&g_deg[edst(ei, e)], 1);
}
__global__ void k_scan_block() {
    __shared__ int s[SCAN_B];
    int i = blockIdx.x * SCAN_B + threadIdx.x;
    int v = (i < N_NODES) ? g_deg[i] : 0;
    s[threadIdx.x] = v;
    __syncthreads();
    for (int off = 1; off < SCAN_B; off <<= 1) {
        int t = (threadIdx.x >= off) ? s[threadIdx.x - off] : 0;
        __syncthreads();
        s[threadIdx.x] += t;
        __syncthreads();
    }
    if (i < N_NODES) g_rowptr[i] = s[threadIdx.x] - v;
    if (threadIdx.x == SCAN_B - 1) g_part[blockIdx.x] = s[SCAN_B - 1];
}
__global__ void k_scan_add() {
    __shared__ int sp[256];
    int t = threadIdx.x;
    if (t < 256) sp[t] = (t < SCAN_NB) ? g_part[t] : 0;
    __syncthreads();
    for (int off = 1; off < 256; off <<= 1) {
        int v = (t < 256 && t >= off) ? sp[t - off] : 0;
        __syncthreads();
        if (t < 256) sp[t] += v;
        __syncthreads();
    }
    int offset = (blockIdx.x == 0) ? 0 : sp[blockIdx.x - 1];
    int i = blockIdx.x * SCAN_B + t;
    if (i < N_NODES) {
        int r = g_rowptr[i] + offset;
        g_rowptr[i] = r;
        g_fill[i] = r;
    }
    if (i == 0) g_rowptr[N_NODES] = N_EDGES;
}
__global__ void k_scatter(const void* ei) {
    int e = blockIdx.x * blockDim.x + threadIdx.x;
    if (e < N_EDGES) {
        int d = edst(ei, e);
        int p = atomicAdd(&g_fill[d], 1);
        g_col[p] = esrc(ei, e);
    }
}

// ---------------- k_agg: warp-per-node gather (HIGH occupancy) -----------
// Lane covers col pair (2l, 2l+1). fp16 source, 4 edges in flight.
// Emits split-bf16 A row: [agg(0..63) | self(64..127)] as u32 pairs.
__global__ void __launch_bounds__(256) k_agg(const float* __restrict__ x) {
    int warp = (blockIdx.x * blockDim.x + threadIdx.x) >> 5;
    int lane = threadIdx.x & 31;
    if (warp >= N_NODES) return;
    float a0 = 0.f, a1 = 0.f, b0 = 0.f, b1v = 0.f;
    float c0 = 0.f, c1 = 0.f, d0 = 0.f, d1 = 0.f;
    int s0 = g_rowptr[warp], s1 = g_rowptr[warp + 1];
    int e = s0;
    for (; e + 3 < s1; e += 4) {
        uint32_t p0 = g_xh[g_col[e] * 32 + lane];
        uint32_t p1 = g_xh[g_col[e + 1] * 32 + lane];
        uint32_t p2 = g_xh[g_col[e + 2] * 32 + lane];
        uint32_t p3 = g_xh[g_col[e + 3] * 32 + lane];
        float2 f0 = __half22float2(*(__half2*)&p0);
        float2 f1 = __half22float2(*(__half2*)&p1);
        float2 f2 = __half22float2(*(__half2*)&p2);
        float2 f3 = __half22float2(*(__half2*)&p3);
        a0 += f0.x; a1 += f0.y;
        b0 += f1.x; b1v += f1.y;
        c0 += f2.x; c1 += f2.y;
        d0 += f3.x; d1 += f3.y;
    }
    for (; e < s1; e++) {
        uint32_t p0 = g_xh[g_col[e] * 32 + lane];
        float2 f0 = __half22float2(*(__half2*)&p0);
        a0 += f0.x; a1 += f0.y;
    }
    a0 += b0 + c0 + d0;
    a1 += b1v + c1 + d1;
    float inv = 1.f / (float)max(s1 - s0, 1);
    a0 *= inv; a1 *= inv;
    __nv_bfloat16 h0, l0, h1, l1;
    split_bf16(a0, h0, l0); split_bf16(a1, h1, l1);
    g_ah[(size_t)warp * 64 + lane] = pack_bf2(h0, h1);
    g_al[(size_t)warp * 64 + lane] = pack_bf2(l0, l1);
    uint32_t sp = g_xh[(size_t)warp * 32 + lane];
    float2 sv = __half22float2(*(__half2*)&sp);
    split_bf16(sv.x, h0, l0); split_bf16(sv.y, h1, l1);
    g_ah[(size_t)warp * 64 + 32 + lane] = pack_bf2(h0, h1);
    g_al[(size_t)warp * 64 + 32 + lane] = pack_bf2(l0, l1);
}

// ---------------- k_mma: PERSISTENT; weights staged once, loop tiles ------
__global__ void __launch_bounds__(512) k_mma(const float* __restrict__ b1) {
    extern __shared__ char dsm[];
    __nv_bfloat16* sAh = (__nv_bfloat16*)(dsm + SM_AH);
    __nv_bfloat16* sAl = (__nv_bfloat16*)(dsm + SM_AL);
    __nv_bfloat16* sW1h = (__nv_bfloat16*)(dsm + SM_W1H);
    __nv_bfloat16* sW1l = (__nv_bfloat16*)(dsm + SM_W1L);
    __nv_bfloat16* sW2h = (__nv_bfloat16*)(dsm + SM_W2H);
    __nv_bfloat16* sW2l = (__nv_bfloat16*)(dsm + SM_W2L);
    float* sB = (float*)(dsm + SM_BIAS);

    int tid = threadIdx.x, wid = tid >> 5, lane = tid & 31;

    // ---- stage weights ONCE ----
    for (int i = tid; i < 128 * 16; i += 512) {
        int r = i >> 4, c8 = i & 15;
        *(uint4*)((char*)sW1h + r * (LDS_ROW * 2) + c8 * 16) = *(const uint4*)(g_w1h + r * 64 + c8 * 4);
        *(uint4*)((char*)sW1l + r * (LDS_ROW * 2) + c8 * 16) = *(const uint4*)(g_w1l + r * 64 + c8 * 4);
    }
    for (int i = tid; i < W2ROWS * 16; i += 512) {
        int r = i >> 4, c8 = i & 15;
        *(uint4*)((char*)sW2h + r * (LDS_ROW * 2) + c8 * 16) = *(const uint4*)(g_w2h + r * 64 + c8 * 4);
        *(uint4*)((char*)sW2l + r * (LDS_ROW * 2) + c8 * 16) = *(const uint4*)(g_w2l + r * 64 + c8 * 4);
    }
    if (tid < DHID) sB[tid] = b1[tid];

    // warp-tile coordinates (constant across tiles)
    int Rb = (wid & 3) * 32;
    int Nb = (wid >> 2) * 32;
    int Rb2 = (wid & 7) * 16;
    int Nb2 = (wid >> 3) * 40;
    int qr = lane >> 2;
    int qc = 2 * (lane & 3);

    for (int tile = blockIdx.x; tile < N_TILES; tile += MMA_GRID) {
        int base = tile * TILE_M;
        __syncthreads();  // prev tile fully consumed before overwriting A
        // ---- stage A tile (coalesced from k_agg output) ----
        for (int i = tid; i < 128 * 16; i += 512) {
            int r = i >> 4, c8 = i & 15;
            int n = base + r;
            uint4 vh = make_uint4(0, 0, 0, 0), vl = make_uint4(0, 0, 0, 0);
            if (n < N_NODES) {
                vh = *(const uint4*)(g_ah + (size_t)n * 64 + c8 * 4);
                vl = *(const uint4*)(g_al + (size_t)n * 64 + c8 * 4);
            }
            *(uint4*)((char*)sAh + r * (LDS_ROW * 2) + c8 * 16) = vh;
            *(uint4*)((char*)sAl + r * (LDS_ROW * 2) + c8 * 16) = vl;
        }
        __syncthreads();

        // ---- GEMM1: 128x128, warp grid 4(M) x 4(N), warp tile 32x32 ----
        float acc[2][4][4];
#pragma unroll
        for (int mt = 0; mt < 2; mt++)
#pragma unroll
            for (int nt = 0; nt < 4; nt++)
#pragma unroll
                for (int j = 0; j < 4; j++) acc[mt][nt][j] = 0.f;

        for (int ks = 0; ks < 8; ks++) {
            int kc = ks * 16 + qc;
            uint32_t ah[2][4], al[2][4];
#pragma unroll
            for (int mt = 0; mt < 2; mt++) {
                int r = Rb + mt * 16 + qr;
                ah[mt][0] = *(const uint32_t*)(sAh + r * LDS_ROW + kc);
                ah[mt][1] = *(const uint32_t*)(sAh + (r + 8) * LDS_ROW + kc);
                ah[mt][2] = *(const uint32_t*)(sAh + r * LDS_ROW + kc + 8);
                ah[mt][3] = *(const uint32_t*)(sAh + (r + 8) * LDS_ROW + kc + 8);
                al[mt][0] = *(const uint32_t*)(sAl + r * LDS_ROW + kc);
                al[mt][1] = *(const uint32_t*)(sAl + (r + 8) * LDS_ROW + kc);
                al[mt][2] = *(const uint32_t*)(sAl + r * LDS_ROW + kc + 8);
                al[mt][3] = *(const uint32_t*)(sAl + (r + 8) * LDS_ROW + kc + 8);
            }
#pragma unroll
            for (int nt = 0; nt < 4; nt++) {
                int nn = Nb + nt * 8 + qr;
                uint32_t bh0 = *(const uint32_t*)(sW1h + nn * LDS_ROW + kc);
                uint32_t bh1 = *(const uint32_t*)(sW1h + nn * LDS_ROW + kc + 8);
                uint32_t bl0 = *(const uint32_t*)(sW1l + nn * LDS_ROW + kc);
                uint32_t bl1 = *(const uint32_t*)(sW1l + nn * LDS_ROW + kc + 8);
#pragma unroll
                for (int mt = 0; mt < 2; mt++) {
                    mma16816(acc[mt][nt], ah[mt], bh0, bh1);
                    mma16816(acc[mt][nt], al[mt], bh0, bh1);
                    mma16816(acc[mt][nt], ah[mt], bl0, bl1);
                }
            }
        }
        __syncthreads();  // done reading A; safe to overwrite with h1

        // ---- epilogue 1: bias + relu + resplit -> sAh/sAl (h1 tile) ----
#pragma unroll
        for (int mt = 0; mt < 2; mt++) {
#pragma unroll
            for (int nt = 0; nt < 4; nt++) {
                int c = Nb + nt * 8 + qc;
                float bv0 = sB[c], bv1 = sB[c + 1];
#pragma unroll
                for (int half = 0; half < 2; half++) {
                    int r = Rb + mt * 16 + qr + half * 8;
                    float v0 = acc[mt][nt][2 * half] + bv0;
                    float v1 = acc[mt][nt][2 * half + 1] + bv1;
                    v0 = v0 > 0.f ? v0 : 0.f;
                    v1 = v1 > 0.f ? v1 : 0.f;
                    __nv_bfloat16 h0, h1, l0, l1;
                    split_bf16(v0, h0, l0);
                    split_bf16(v1, h1, l1);
                    *(uint32_t*)(sAh + r * LDS_ROW + c) = pack_bf2(h0, h1);
                    *(uint32_t*)(sAl + r * LDS_ROW + c) = pack_bf2(l0, l1);
                }
            }
        }
        __syncthreads();

        // ---- GEMM2: 128x80, warp grid 8(M) x 2(N), warp tile 16x40 ----
        float acc2[5][4];
#pragma unroll
        for (int nt = 0; nt < 5; nt++)
#pragma unroll
            for (int j = 0; j < 4; j++) acc2[nt][j] = 0.f;

        for (int ks = 0; ks < 8; ks++) {
            int kc = ks * 16 + qc;
            int r = Rb2 + qr;
            uint32_t ah[4], al[4];
            ah[0] = *(const uint32_t*)(sAh + r * LDS_ROW + kc);
            ah[1] = *(const uint32_t*)(sAh + (r + 8) * LDS_ROW + kc);
            ah[2] = *(const uint32_t*)(sAh + r * LDS_ROW + kc + 8);
            ah[3] = *(const uint32_t*)(sAh + (r + 8) * LDS_ROW + kc + 8);
            al[0] = *(const uint32_t*)(sAl + r * LDS_ROW + kc);
            al[1] = *(const uint32_t*)(sAl + (r + 8) * LDS_ROW + kc);
            al[2] = *(const uint32_t*)(sAl + r * LDS_ROW + kc + 8);
            al[3] = *(const uint32_t*)(sAl + (r + 8) * LDS_ROW + kc + 8);
#pragma unroll
            for (int nt = 0; nt < 5; nt++) {
                int nn = Nb2 + nt * 8 + qr;
                uint32_t bh0 = *(const uint32_t*)(sW2h + nn * LDS_ROW + kc);
                uint32_t bh1 = *(const uint32_t*)(sW2h + nn * LDS_ROW + kc + 8);
                uint32_t bl0 = *(const uint32_t*)(sW2l + nn * LDS_ROW + kc);
                uint32_t bl1 = *(const uint32_t*)(sW2l + nn * LDS_ROW + kc + 8);
                mma16816(acc2[nt], ah, bh0, bh1);
                mma16816(acc2[nt], al, bh0, bh1);
                mma16816(acc2[nt], ah, bl0, bl1);
            }
        }

        // ---- epilogue 2: write y2l (half2) / y2r (fp32) ----
#pragma unroll
        for (int nt = 0; nt < 5; nt++) {
            int c = Nb2 + nt * 8 + qc;  // 0..78 even
            int n0 = base + Rb2 + qr;
            int n1 = n0 + 8;
            if (c < DOUT) {
                __half2 h0 = __floats2half2_rn(acc2[nt][0], acc2[nt][1]);
                __half2 h1 = __floats2half2_rn(acc2[nt][2], acc2[nt][3]);
                if (n0 < N_NODES) g_y2l[(size_t)n0 * Y2L_W32 + (c >> 1)] = *(uint32_t*)&h0;
                if (n1 < N_NODES) g_y2l[(size_t)n1 * Y2L_W32 + (c >> 1)] = *(uint32_t*)&h1;
            } else {
                int cc = c - DOUT;
                if (n0 < N_NODES)
                    *(float2*)&g_y2r[(size_t)n0 * DOUT + cc] = make_float2(acc2[nt][0], acc2[nt][1]);
                if (n1 < N_NODES)
                    *(float2*)&g_y2r[(size_t)n1 * DOUT + cc] = make_float2(acc2[nt][2], acc2[nt][3]);
            }
        }
    }
}

// ---------------- final: out = log_softmax(mean-agg(y2l) + b2 + y2r) ------
// one warp/node; lane l<20 owns output pair (2l, 2l+1); y2l gathered as half2
__global__ void __launch_bounds__(256) k_out(const float* __restrict__ b2,
                                             float* __restrict__ out) {
    int warp = (blockIdx.x * blockDim.x + threadIdx.x) >> 5;
    int lane = threadIdx.x & 31;
    if (warp >= N_NODES) return;
    float a0 = 0.f, a1 = 0.f, b0 = 0.f, b1v = 0.f;
    float c0 = 0.f, c1 = 0.f, d0 = 0.f, d1 = 0.f;
    int s0 = g_rowptr[warp], s1 = g_rowptr[warp + 1];
    int e = s0;
    int ln = (lane < 20) ? lane : 0;
    for (; e + 3 < s1; e += 4) {
        uint32_t p0 = g_y2l[(size_t)g_col[e] * Y2L_W32 + ln];
        uint32_t p1 = g_y2l[(size_t)g_col[e + 1] * Y2L_W32 + ln];
        uint32_t p2 = g_y2l[(size_t)g_col[e + 2] * Y2L_W32 + ln];
        uint32_t p3 = g_y2l[(size_t)g_col[e + 3] * Y2L_W32 + ln];
        float2 f0 = __half22float2(*(__half2*)&p0);
        float2 f1 = __half22float2(*(__half2*)&p1);
        float2 f2 = __half22float2(*(__half2*)&p2);
        float2 f3 = __half22float2(*(__half2*)&p3);
        a0 += f0.x; a1 += f0.y;
        b0 += f1.x; b1v += f1.y;
        c0 += f2.x; c1 += f2.y;
        d0 += f3.x; d1 += f3.y;
    }
    for (; e < s1; e++) {
        uint32_t p0 = g_y2l[(size_t)g_col[e] * Y2L_W32 + ln];
        float2 f0 = __half22float2(*(__half2*)&p0);
        a0 += f0.x; a1 += f0.y;
    }
    a0 += b0 + c0 + d0;
    a1 += b1v + c1 + d1;
    float inv = 1.f / (float)max(s1 - s0, 1);
    size_t nb = (size_t)warp * DOUT;
    float v0 = -INFINITY, v1 = -INFINITY;
    if (lane < 20) {
        v0 = a0 * inv + b2[2 * lane] + g_y2r[nb + 2 * lane];
        v1 = a1 * inv + b2[2 * lane + 1] + g_y2r[nb + 2 * lane + 1];
    }
    float m = fmaxf(v0, v1);
    for (int off = 16; off; off >>= 1)
        m = fmaxf(m, __shfl_xor_sync(0xffffffffu, m, off));
    float s = (lane < 20) ? (expf(v0 - m) + expf(v1 - m)) : 0.f;
    for (int off = 16; off; off >>= 1)
        s += __shfl_xor_sync(0xffffffffu, s, off);
    float lse = m + logf(s);
    if (lane < 20)
        *(float2*)&out[nb + 2 * lane] = make_float2(v0 - lse, v1 - lse);
}

// ---------------- launch --------------------------------------------------
extern "C" void kernel_launch(void* const* d_in, const int* in_sizes, int n_in,
                              void* d_out, int out_size) {
    const float* x = (const float*)d_in[0];
    const void* ei = d_in[1];
    const float* W1l = (const float*)d_in[2];
    const float* b1 = (const float*)d_in[3];
    const float* W1r = (const float*)d_in[4];
    const float* W2l = (const float*)d_in[5];
    const float* b2 = (const float*)d_in[6];
    const float* W2r = (const float*)d_in[7];
    float* out = (float*)d_out;

    cudaFuncSetAttribute(k_mma, cudaFuncAttributeMaxDynamicSharedMemorySize,
                         SM_TOTAL);

    k_init<<<(N_NODES * 32 + 255) / 256, 256>>>((const int*)ei, x, W1l, W1r, W2l, W2r);
    k_hist<<<(N_EDGES + 255) / 256, 256>>>(ei);
    k_scan_block<<<SCAN_NB, SCAN_B>>>();
    k_scan_add<<<SCAN_NB, SCAN_B>>>();
    k_scatter<<<(N_EDGES + 255) / 256, 256>>>(ei);

    k_agg<<<(N_NODES * 32 + 255) / 256, 256>>>(x);
    k_mma<<<MMA_GRID, 512, SM_TOTAL>>>(b1);
    k_out<<<(N_NODES * 32 + 255) / 256, 256>>>(b2, out);
}

// round 12
// speedup vs baseline: 1.2749x; 1.0803x over previous
#include <cuda_runtime.h>
#include <cuda_bf16.h>
#include <cuda_fp16.h>
#include <math.h>
#include <stdint.h>

#define N_NODES 100000
#define N_EDGES 1600000
#define DIN 64
#define DHID 128
#define DOUT 40
#define Y2L_W32 24  // y2l row stride in uint32 (48 halves = 96B)
#define SCAN_B 512
#define SCAN_NB ((N_NODES + SCAN_B - 1) / SCAN_B)
#define TILE_M 128
#define N_TILES ((N_NODES + TILE_M - 1) / TILE_M)  // 782
#define W2ROWS 80
#define LDS_ROW 136  // bf16 elems per SMEM row (128 + 8 pad) -> conflict-free frags
#define MMA_GRID 148 // persistent CTAs

// SMEM byte offsets for MMA kernel
#define SM_AH 0
#define SM_AL 34816
#define SM_W1H 69632
#define SM_W1L 104448
#define SM_W2H 139264
#define SM_W2L 161024
#define SM_BIAS 182784
#define SM_TOTAL 183424

// ---------------- device scratch ----------------
__device__ int g_is64;
__device__ int g_deg[N_NODES];
__device__ int g_rowptr[N_NODES + 1];
__device__ int g_fill[N_NODES];
__device__ int g_col[N_EDGES];
__device__ int g_part[256];
__device__ uint32_t g_xh[(size_t)N_NODES * 32];  // x as half2 pairs [node][32]
__device__ uint32_t g_ah[(size_t)N_NODES * 32];  // agg hi: bf16x2 [node][32] (64 cols)
__device__ uint32_t g_al[(size_t)N_NODES * 32];  // agg lo
__device__ uint32_t g_w1h[DHID * 64], g_w1l[DHID * 64];      // [128 out][128 k] bf16x2
__device__ uint32_t g_w2h[W2ROWS * 64], g_w2l[W2ROWS * 64];  // [80 out][128 k]
__device__ uint32_t g_y2l[(size_t)N_NODES * Y2L_W32 + 32];   // half2, padded tail
__device__ float g_y2r[(size_t)N_NODES * DOUT];

// ---------------- helpers ----------------
__device__ __forceinline__ void mma16816(float* c, const uint32_t* a,
                                         uint32_t b0, uint32_t b1) {
    asm volatile(
        "mma.sync.aligned.m16n8k16.row.col.f32.bf16.bf16.f32 "
        "{%0,%1,%2,%3}, {%4,%5,%6,%7}, {%8,%9}, {%0,%1,%2,%3};"
        : "+f"(c[0]), "+f"(c[1]), "+f"(c[2]), "+f"(c[3])
        : "r"(a[0]), "r"(a[1]), "r"(a[2]), "r"(a[3]), "r"(b0), "r"(b1));
}
__device__ __forceinline__ void split_bf16(float v, __nv_bfloat16& h, __nv_bfloat16& l) {
    h = __float2bfloat16_rn(v);
    l = __float2bfloat16_rn(v - __bfloat162float(h));
}
__device__ __forceinline__ uint32_t pack_bf2(__nv_bfloat16 a, __nv_bfloat16 b) {
    __nv_bfloat162 p = __nv_bfloat162(a, b);
    return *(uint32_t*)&p;
}

// ---------------- edge index access (int64 or int32, runtime-detected) ----
__device__ __forceinline__ int edst(const void* ei, int e) {
    return g_is64 ? (int)((const long long*)ei)[(size_t)N_EDGES + e]
                  : ((const int*)ei)[(size_t)N_EDGES + e];
}
__device__ __forceinline__ int esrc(const void* ei, int e) {
    return g_is64 ? (int)((const long long*)ei)[e] : ((const int*)ei)[e];
}

// init degrees + dtype detect + weight split + x->fp16 conversion
__global__ void k_init(const int* ei, const float* __restrict__ x,
                       const float* __restrict__ W1l, const float* __restrict__ W1r,
                       const float* __restrict__ W2l, const float* __restrict__ W2r) {
    int i = blockIdx.x * blockDim.x + threadIdx.x;
    if (i < N_NODES) g_deg[i] = 0;
    if (i < N_NODES * 32) {
        int n = i >> 5, q = i & 31;
        float2 v = *(const float2*)&x[(size_t)n * DIN + 2 * q];
        __half2 h = __floats2half2_rn(v.x, v.y);
        g_xh[(size_t)n * 32 + q] = *(uint32_t*)&h;
    }
    int tot1 = DHID * 64;
    if (i < tot1) {
        int o = i >> 6, c = 2 * (i & 63);
        float v0 = (c < 64) ? W1l[o * 64 + c] : W1r[o * 64 + c - 64];
        float v1 = (c < 64) ? W1l[o * 64 + c + 1] : W1r[o * 64 + c - 63];
        __nv_bfloat16 h0, h1, l0, l1;
        split_bf16(v0, h0, l0); split_bf16(v1, h1, l1);
        g_w1h[i] = pack_bf2(h0, h1);
        g_w1l[i] = pack_bf2(l0, l1);
    } else if (i < tot1 + W2ROWS * 64) {
        int j = i - tot1;
        int o = j >> 6, c = 2 * (j & 63);
        float v0 = (o < DOUT) ? W2l[o * DHID + c] : W2r[(o - DOUT) * DHID + c];
        float v1 = (o < DOUT) ? W2l[o * DHID + c + 1] : W2r[(o - DOUT) * DHID + c + 1];
        __nv_bfloat16 h0, h1, l0, l1;
        split_bf16(v0, h0, l0); split_bf16(v1, h1, l1);
        g_w2h[j] = pack_bf2(h0, h1);
        g_w2l[j] = pack_bf2(l0, l1);
    }
    if (blockIdx.x == 0) {
        bool ok = true;
        for (int j = threadIdx.x; j < 4096; j += blockDim.x)
            if (ei[2 * j + 1] != 0) ok = false;
        int all = __syncthreads_and((int)ok);
        if (threadIdx.x == 0) g_is64 = all ? 1 : 0;
    }
}
__global__ void k_hist(const void* ei) {
    int e = blockIdx.x * blockDim.x + threadIdx.x;
    if (e < N_EDGES) atomicAdd(&g_deg[edst(ei, e)], 1);
}
__global__ void k_scan_block() {
    __shared__ int s[SCAN_B];
    int i = blockIdx.x * SCAN_B + threadIdx.x;
    int v = (i < N_NODES) ? g_deg[i] : 0;
    s[threadIdx.x] = v;
    __syncthreads();
    for (int off = 1; off < SCAN_B; off <<= 1) {
        int t = (threadIdx.x >= off) ? s[threadIdx.x - off] : 0;
        __syncthreads();
        s[threadIdx.x] += t;
        __syncthreads();
    }
    if (i < N_NODES) g_rowptr[i] = s[threadIdx.x] - v;
    if (threadIdx.x == SCAN_B - 1) g_part[blockIdx.x] = s[SCAN_B - 1];
}
__global__ void k_scan_add() {
    __shared__ int sp[256];
    int t = threadIdx.x;
    if (t < 256) sp[t] = (t < SCAN_NB) ? g_part[t] : 0;
    __syncthreads();
    for (int off = 1; off < 256; off <<= 1) {
        int v = (t < 256 && t >= off) ? sp[t - off] : 0;
        __syncthreads();
        if (t < 256) sp[t] += v;
        __syncthreads();
    }
    int offset = (blockIdx.x == 0) ? 0 : sp[blockIdx.x - 1];
    int i = blockIdx.x * SCAN_B + t;
    if (i < N_NODES) {
        int r = g_rowptr[i] + offset;
        g_rowptr[i] = r;
        g_fill[i] = r;
    }
    if (i == 0) g_rowptr[N_NODES] = N_EDGES;
}
__global__ void k_scatter(const void* ei) {
    int e = blockIdx.x * blockDim.x + threadIdx.x;
    if (e < N_EDGES) {
        int d = edst(ei, e);
        int p = atomicAdd(&g_fill[d], 1);
        g_col[p] = esrc(ei, e);
    }
}

// ---------------- k_agg: 2 nodes per warp, half-warp per node ------------
// Lane (hl = lane&15) covers col quad (4hl..4hl+3) via one uint2 per edge.
// 8 edges in flight per warp (2 nodes x 4-deep unroll).
__global__ void __launch_bounds__(256) k_agg() {
    int warp = (blockIdx.x * blockDim.x + threadIdx.x) >> 5;
    int lane = threadIdx.x & 31;
    int half = lane >> 4, hl = lane & 15;
    int n = 2 * warp + half;
    if (n >= N_NODES) return;
    float a0 = 0.f, a1 = 0.f, a2 = 0.f, a3 = 0.f;
    float b0 = 0.f, b1v = 0.f, b2v = 0.f, b3 = 0.f;
    float c0 = 0.f, c1 = 0.f, c2 = 0.f, c3 = 0.f;
    float d0 = 0.f, d1 = 0.f, d2 = 0.f, d3 = 0.f;
    int s0 = g_rowptr[n], s1 = g_rowptr[n + 1];
    int e = s0;
    for (; e + 3 < s1; e += 4) {
        uint2 p0 = *(const uint2*)(g_xh + (size_t)g_col[e] * 32 + 2 * hl);
        uint2 p1 = *(const uint2*)(g_xh + (size_t)g_col[e + 1] * 32 + 2 * hl);
        uint2 p2 = *(const uint2*)(g_xh + (size_t)g_col[e + 2] * 32 + 2 * hl);
        uint2 p3 = *(const uint2*)(g_xh + (size_t)g_col[e + 3] * 32 + 2 * hl);
        float2 f;
        f = __half22float2(*(__half2*)&p0.x); a0 += f.x; a1 += f.y;
        f = __half22float2(*(__half2*)&p0.y); a2 += f.x; a3 += f.y;
        f = __half22float2(*(__half2*)&p1.x); b0 += f.x; b1v += f.y;
        f = __half22float2(*(__half2*)&p1.y); b2v += f.x; b3 += f.y;
        f = __half22float2(*(__half2*)&p2.x); c0 += f.x; c1 += f.y;
        f = __half22float2(*(__half2*)&p2.y); c2 += f.x; c3 += f.y;
        f = __half22float2(*(__half2*)&p3.x); d0 += f.x; d1 += f.y;
        f = __half22float2(*(__half2*)&p3.y); d2 += f.x; d3 += f.y;
    }
    for (; e < s1; e++) {
        uint2 p0 = *(const uint2*)(g_xh + (size_t)g_col[e] * 32 + 2 * hl);
        float2 f;
        f = __half22float2(*(__half2*)&p0.x); a0 += f.x; a1 += f.y;
        f = __half22float2(*(__half2*)&p0.y); a2 += f.x; a3 += f.y;
    }
    a0 += b0 + c0 + d0;
    a1 += b1v + c1 + d1;
    a2 += b2v + c2 + d2;
    a3 += b3 + c3 + d3;
    float inv = 1.f / (float)max(s1 - s0, 1);
    a0 *= inv; a1 *= inv; a2 *= inv; a3 *= inv;
    __nv_bfloat16 h0, l0, h1, l1, h2, l2, h3, l3;
    split_bf16(a0, h0, l0); split_bf16(a1, h1, l1);
    split_bf16(a2, h2, l2); split_bf16(a3, h3, l3);
    uint2 oh = make_uint2(pack_bf2(h0, h1), pack_bf2(h2, h3));
    uint2 ol = make_uint2(pack_bf2(l0, l1), pack_bf2(l2, l3));
    *(uint2*)(g_ah + (size_t)n * 32 + 2 * hl) = oh;
    *(uint2*)(g_al + (size_t)n * 32 + 2 * hl) = ol;
}

// ---------------- k_mma: PERSISTENT; weights staged once, loop tiles ------
__global__ void __launch_bounds__(512) k_mma(const float* __restrict__ b1) {
    extern __shared__ char dsm[];
    __nv_bfloat16* sAh = (__nv_bfloat16*)(dsm + SM_AH);
    __nv_bfloat16* sAl = (__nv_bfloat16*)(dsm + SM_AL);
    __nv_bfloat16* sW1h = (__nv_bfloat16*)(dsm + SM_W1H);
    __nv_bfloat16* sW1l = (__nv_bfloat16*)(dsm + SM_W1L);
    __nv_bfloat16* sW2h = (__nv_bfloat16*)(dsm + SM_W2H);
    __nv_bfloat16* sW2l = (__nv_bfloat16*)(dsm + SM_W2L);
    float* sB = (float*)(dsm + SM_BIAS);

    int tid = threadIdx.x, wid = tid >> 5, lane = tid & 31;

    // ---- stage weights ONCE ----
    for (int i = tid; i < 128 * 16; i += 512) {
        int r = i >> 4, c8 = i & 15;
        *(uint4*)((char*)sW1h + r * (LDS_ROW * 2) + c8 * 16) = *(const uint4*)(g_w1h + r * 64 + c8 * 4);
        *(uint4*)((char*)sW1l + r * (LDS_ROW * 2) + c8 * 16) = *(const uint4*)(g_w1l + r * 64 + c8 * 4);
    }
    for (int i = tid; i < W2ROWS * 16; i += 512) {
        int r = i >> 4, c8 = i & 15;
        *(uint4*)((char*)sW2h + r * (LDS_ROW * 2) + c8 * 16) = *(const uint4*)(g_w2h + r * 64 + c8 * 4);
        *(uint4*)((char*)sW2l + r * (LDS_ROW * 2) + c8 * 16) = *(const uint4*)(g_w2l + r * 64 + c8 * 4);
    }
    if (tid < DHID) sB[tid] = b1[tid];

    // warp-tile coordinates (constant across tiles)
    int Rb = (wid & 3) * 32;
    int Nb = (wid >> 2) * 32;
    int Rb2 = (wid & 7) * 16;
    int Nb2 = (wid >> 3) * 40;
    int qr = lane >> 2;
    int qc = 2 * (lane & 3);

    for (int tile = blockIdx.x; tile < N_TILES; tile += MMA_GRID) {
        int base = tile * TILE_M;
        __syncthreads();  // prev tile fully consumed before overwriting A
        // ---- stage A tile: agg half from g_ah/g_al, self half from g_xh ----
        for (int i = tid; i < 128 * 8; i += 512) {
            int r = i >> 3, c8 = i & 7;
            int n = base + r;
            uint4 vh = make_uint4(0, 0, 0, 0), vl = make_uint4(0, 0, 0, 0);
            if (n < N_NODES) {
                vh = *(const uint4*)(g_ah + (size_t)n * 32 + c8 * 4);
                vl = *(const uint4*)(g_al + (size_t)n * 32 + c8 * 4);
            }
            *(uint4*)((char*)sAh + r * (LDS_ROW * 2) + c8 * 16) = vh;
            *(uint4*)((char*)sAl + r * (LDS_ROW * 2) + c8 * 16) = vl;
        }
        // self half: split fp16 x on the fly into cols 64..127
        for (int i = tid; i < 128 * 16; i += 512) {
            int r = i >> 4, q2 = i & 15;  // q2: pair of half2 words
            int n = base + r;
            uint2 p = make_uint2(0, 0);
            if (n < N_NODES) p = *(const uint2*)(g_xh + (size_t)n * 32 + 2 * q2);
            float2 f0 = __half22float2(*(__half2*)&p.x);
            float2 f1 = __half22float2(*(__half2*)&p.y);
            __nv_bfloat16 h0, l0, h1, l1, h2, l2, h3, l3;
            split_bf16(f0.x, h0, l0); split_bf16(f0.y, h1, l1);
            split_bf16(f1.x, h2, l2); split_bf16(f1.y, h3, l3);
            uint2 oh = make_uint2(pack_bf2(h0, h1), pack_bf2(h2, h3));
            uint2 ol = make_uint2(pack_bf2(l0, l1), pack_bf2(l2, l3));
            *(uint2*)(sAh + r * LDS_ROW + 64 + 4 * q2) = oh;
            *(uint2*)(sAl + r * LDS_ROW + 64 + 4 * q2) = ol;
        }
        __syncthreads();

        // ---- GEMM1: 128x128, warp grid 4(M) x 4(N), warp tile 32x32 ----
        float acc[2][4][4];
#pragma unroll
        for (int mt = 0; mt < 2; mt++)
#pragma unroll
            for (int nt = 0; nt < 4; nt++)
#pragma unroll
                for (int j = 0; j < 4; j++) acc[mt][nt][j] = 0.f;

        for (int ks = 0; ks < 8; ks++) {
            int kc = ks * 16 + qc;
            uint32_t ah[2][4], al[2][4];
#pragma unroll
            for (int mt = 0; mt < 2; mt++) {
                int r = Rb + mt * 16 + qr;
                ah[mt][0] = *(const uint32_t*)(sAh + r * LDS_ROW + kc);
                ah[mt][1] = *(const uint32_t*)(sAh + (r + 8) * LDS_ROW + kc);
                ah[mt][2] = *(const uint32_t*)(sAh + r * LDS_ROW + kc + 8);
                ah[mt][3] = *(const uint32_t*)(sAh + (r + 8) * LDS_ROW + kc + 8);
                al[mt][0] = *(const uint32_t*)(sAl + r * LDS_ROW + kc);
                al[mt][1] = *(const uint32_t*)(sAl + (r + 8) * LDS_ROW + kc);
                al[mt][2] = *(const uint32_t*)(sAl + r * LDS_ROW + kc + 8);
                al[mt][3] = *(const uint32_t*)(sAl + (r + 8) * LDS_ROW + kc + 8);
            }
#pragma unroll
            for (int nt = 0; nt < 4; nt++) {
                int nn = Nb + nt * 8 + qr;
                uint32_t bh0 = *(const uint32_t*)(sW1h + nn * LDS_ROW + kc);
                uint32_t bh1 = *(const uint32_t*)(sW1h + nn * LDS_ROW + kc + 8);
                uint32_t bl0 = *(const uint32_t*)(sW1l + nn * LDS_ROW + kc);
                uint32_t bl1 = *(const uint32_t*)(sW1l + nn * LDS_ROW + kc + 8);
#pragma unroll
                for (int mt = 0; mt < 2; mt++) {
                    mma16816(acc[mt][nt], ah[mt], bh0, bh1);
                    mma16816(acc[mt][nt], al[mt], bh0, bh1);
                    mma16816(acc[mt][nt], ah[mt], bl0, bl1);
                }
            }
        }
        __syncthreads();  // done reading A; safe to overwrite with h1

        // ---- epilogue 1: bias + relu + resplit -> sAh/sAl (h1 tile) ----
#pragma unroll
        for (int mt = 0; mt < 2; mt++) {
#pragma unroll
            for (int nt = 0; nt < 4; nt++) {
                int c = Nb + nt * 8 + qc;
                float bv0 = sB[c], bv1 = sB[c + 1];
#pragma unroll
                for (int half = 0; half < 2; half++) {
                    int r = Rb + mt * 16 + qr + half * 8;
                    float v0 = acc[mt][nt][2 * half] + bv0;
                    float v1 = acc[mt][nt][2 * half + 1] + bv1;
                    v0 = v0 > 0.f ? v0 : 0.f;
                    v1 = v1 > 0.f ? v1 : 0.f;
                    __nv_bfloat16 h0, h1, l0, l1;
                    split_bf16(v0, h0, l0);
                    split_bf16(v1, h1, l1);
                    *(uint32_t*)(sAh + r * LDS_ROW + c) = pack_bf2(h0, h1);
                    *(uint32_t*)(sAl + r * LDS_ROW + c) = pack_bf2(l0, l1);
                }
            }
        }
        __syncthreads();

        // ---- GEMM2: 128x80, warp grid 8(M) x 2(N), warp tile 16x40 ----
        float acc2[5][4];
#pragma unroll
        for (int nt = 0; nt < 5; nt++)
#pragma unroll
            for (int j = 0; j < 4; j++) acc2[nt][j] = 0.f;

        for (int ks = 0; ks < 8; ks++) {
            int kc = ks * 16 + qc;
            int r = Rb2 + qr;
            uint32_t ah[4], al[4];
            ah[0] = *(const uint32_t*)(sAh + r * LDS_ROW + kc);
            ah[1] = *(const uint32_t*)(sAh + (r + 8) * LDS_ROW + kc);
            ah[2] = *(const uint32_t*)(sAh + r * LDS_ROW + kc + 8);
            ah[3] = *(const uint32_t*)(sAh + (r + 8) * LDS_ROW + kc + 8);
            al[0] = *(const uint32_t*)(sAl + r * LDS_ROW + kc);
            al[1] = *(const uint32_t*)(sAl + (r + 8) * LDS_ROW + kc);
            al[2] = *(const uint32_t*)(sAl + r * LDS_ROW + kc + 8);
            al[3] = *(const uint32_t*)(sAl + (r + 8) * LDS_ROW + kc + 8);
#pragma unroll
            for (int nt = 0; nt < 5; nt++) {
                int nn = Nb2 + nt * 8 + qr;
                uint32_t bh0 = *(const uint32_t*)(sW2h + nn * LDS_ROW + kc);
                uint32_t bh1 = *(const uint32_t*)(sW2h + nn * LDS_ROW + kc + 8);
                uint32_t bl0 = *(const uint32_t*)(sW2l + nn * LDS_ROW + kc);
                uint32_t bl1 = *(const uint32_t*)(sW2l + nn * LDS_ROW + kc + 8);
                mma16816(acc2[nt], ah, bh0, bh1);
                mma16816(acc2[nt], al, bh0, bh1);
                mma16816(acc2[nt], ah, bl0, bl1);
            }
        }

        // ---- epilogue 2: write y2l (half2) / y2r (fp32) ----
#pragma unroll
        for (int nt = 0; nt < 5; nt++) {
            int c = Nb2 + nt * 8 + qc;  // 0..78 even
            int n0 = base + Rb2 + qr;
            int n1 = n0 + 8;
            if (c < DOUT) {
                __half2 h0 = __floats2half2_rn(acc2[nt][0], acc2[nt][1]);
                __half2 h1 = __floats2half2_rn(acc2[nt][2], acc2[nt][3]);
                if (n0 < N_NODES) g_y2l[(size_t)n0 * Y2L_W32 + (c >> 1)] = *(uint32_t*)&h0;
                if (n1 < N_NODES) g_y2l[(size_t)n1 * Y2L_W32 + (c >> 1)] = *(uint32_t*)&h1;
            } else {
                int cc = c - DOUT;
                if (n0 < N_NODES)
                    *(float2*)&g_y2r[(size_t)n0 * DOUT + cc] = make_float2(acc2[nt][0], acc2[nt][1]);
                if (n1 < N_NODES)
                    *(float2*)&g_y2r[(size_t)n1 * DOUT + cc] = make_float2(acc2[nt][2], acc2[nt][3]);
            }
        }
    }
}

// ---------------- final: out = log_softmax(mean-agg(y2l) + b2 + y2r) ------
// one warp/node; lane l<20 owns output pair (2l, 2l+1); y2l gathered as half2
__global__ void __launch_bounds__(256) k_out(const float* __restrict__ b2,
                                             float* __restrict__ out) {
    int warp = (blockIdx.x * blockDim.x + threadIdx.x) >> 5;
    int lane = threadIdx.x & 31;
    if (warp >= N_NODES) return;
    float a0 = 0.f, a1 = 0.f, b0 = 0.f, b1v = 0.f;
    float c0 = 0.f, c1 = 0.f, d0 = 0.f, d1 = 0.f;
    int s0 = g_rowptr[warp], s1 = g_rowptr[warp + 1];
    int e = s0;
    int ln = (lane < 20) ? lane : 0;
    for (; e + 3 < s1; e += 4) {
        uint32_t p0 = g_y2l[(size_t)g_col[e] * Y2L_W32 + ln];
        uint32_t p1 = g_y2l[(size_t)g_col[e + 1] * Y2L_W32 + ln];
        uint32_t p2 = g_y2l[(size_t)g_col[e + 2] * Y2L_W32 + ln];
        uint32_t p3 = g_y2l[(size_t)g_col[e + 3] * Y2L_W32 + ln];
        float2 f0 = __half22float2(*(__half2*)&p0);
        float2 f1 = __half22float2(*(__half2*)&p1);
        float2 f2 = __half22float2(*(__half2*)&p2);
        float2 f3 = __half22float2(*(__half2*)&p3);
        a0 += f0.x; a1 += f0.y;
        b0 += f1.x; b1v += f1.y;
        c0 += f2.x; c1 += f2.y;
        d0 += f3.x; d1 += f3.y;
    }
    for (; e < s1; e++) {
        uint32_t p0 = g_y2l[(size_t)g_col[e] * Y2L_W32 + ln];
        float2 f0 = __half22float2(*(__half2*)&p0);
        a0 += f0.x; a1 += f0.y;
    }
    a0 += b0 + c0 + d0;
    a1 += b1v + c1 + d1;
    float inv = 1.f / (float)max(s1 - s0, 1);
    size_t nb = (size_t)warp * DOUT;
    float v0 = -INFINITY, v1 = -INFINITY;
    if (lane < 20) {
        v0 = a0 * inv + b2[2 * lane] + g_y2r[nb + 2 * lane];
        v1 = a1 * inv + b2[2 * lane + 1] + g_y2r[nb + 2 * lane + 1];
    }
    float m = fmaxf(v0, v1);
    for (int off = 16; off; off >>= 1)
        m = fmaxf(m, __shfl_xor_sync(0xffffffffu, m, off));
    float s = (lane < 20) ? (expf(v0 - m) + expf(v1 - m)) : 0.f;
    for (int off = 16; off; off >>= 1)
        s += __shfl_xor_sync(0xffffffffu, s, off);
    float lse = m + logf(s);
    if (lane < 20)
        *(float2*)&out[nb + 2 * lane] = make_float2(v0 - lse, v1 - lse);
}

// ---------------- launch --------------------------------------------------
extern "C" void kernel_launch(void* const* d_in, const int* in_sizes, int n_in,
                              void* d_out, int out_size) {
    const float* x = (const float*)d_in[0];
    const void* ei = d_in[1];
    const float* W1l = (const float*)d_in[2];
    const float* b1 = (const float*)d_in[3];
    const float* W1r = (const float*)d_in[4];
    const float* W2l = (const float*)d_in[5];
    const float* b2 = (const float*)d_in[6];
    const float* W2r = (const float*)d_in[7];
    float* out = (float*)d_out;

    cudaFuncSetAttribute(k_mma, cudaFuncAttributeMaxDynamicSharedMemorySize,
                         SM_TOTAL);

    k_init<<<(N_NODES * 32 + 255) / 256, 256>>>((const int*)ei, x, W1l, W1r, W2l, W2r);
    k_hist<<<(N_EDGES + 255) / 256, 256>>>(ei);
    k_scan_block<<<SCAN_NB, SCAN_B>>>();
    k_scan_add<<<SCAN_NB, SCAN_B>>>();
    k_scatter<<<(N_EDGES + 255) / 256, 256>>>(ei);

    k_agg<<<(N_NODES * 16 + 255) / 256, 256>>>();
    k_mma<<<MMA_GRID, 512, SM_TOTAL>>>(b1);
    k_out<<<(N_NODES * 32 + 255) / 256, 256>>>(b2, out);
}

// round 13
// speedup vs baseline: 1.3190x; 1.0346x over previous
#include <cuda_runtime.h>
#include <cuda_bf16.h>
#include <cuda_fp16.h>
#include <math.h>
#include <stdint.h>

#define N_NODES 100000
#define N_EDGES 1600000
#define DIN 64
#define DHID 128
#define DOUT 40
#define Y2L_W32 24  // y2l row stride in uint32 (48 halves = 96B)
#define SCAN_B 512
#define SCAN_NB ((N_NODES + SCAN_B - 1) / SCAN_B)
#define TILE_M 128
#define N_TILES ((N_NODES + TILE_M - 1) / TILE_M)  // 782
#define W2ROWS 80
#define LDS_ROW 136  // bf16 elems per SMEM row (128 + 8 pad) -> conflict-free frags
#define MMA_GRID 148 // persistent CTAs

// SMEM byte offsets for MMA kernel
#define SM_AH 0
#define SM_AL 34816
#define SM_W1H 69632
#define SM_W1L 104448
#define SM_W2H 139264
#define SM_W2L 161024
#define SM_BIAS 182784
#define SM_TOTAL 183424

// ---------------- device scratch ----------------
__device__ int g_is64;
__device__ int g_deg[N_NODES];
__device__ int g_rowptr[N_NODES + 1];
__device__ int g_fill[N_NODES];
__device__ int g_col[N_EDGES];
__device__ int g_part[256];
__device__ uint32_t g_xh[(size_t)N_NODES * 32];  // x as half2 pairs [node][32]
__device__ uint32_t g_ah[(size_t)N_NODES * 32];  // agg hi: bf16x2 [node][32] (64 cols)
__device__ uint32_t g_al[(size_t)N_NODES * 32];  // agg lo
__device__ uint32_t g_w1h[DHID * 64], g_w1l[DHID * 64];      // [128 out][128 k] bf16x2
__device__ uint32_t g_w2h[W2ROWS * 64], g_w2l[W2ROWS * 64];  // [80 out][128 k]
__device__ uint32_t g_y2l[(size_t)N_NODES * Y2L_W32 + 32];   // half2, padded tail
__device__ float g_y2r[(size_t)N_NODES * DOUT];

// ---------------- helpers ----------------
__device__ __forceinline__ void mma16816(float* c, const uint32_t* a,
                                         uint32_t b0, uint32_t b1) {
    asm volatile(
        "mma.sync.aligned.m16n8k16.row.col.f32.bf16.bf16.f32 "
        "{%0,%1,%2,%3}, {%4,%5,%6,%7}, {%8,%9}, {%0,%1,%2,%3};"
        : "+f"(c[0]), "+f"(c[1]), "+f"(c[2]), "+f"(c[3])
        : "r"(a[0]), "r"(a[1]), "r"(a[2]), "r"(a[3]), "r"(b0), "r"(b1));
}
__device__ __forceinline__ void split_bf16(float v, __nv_bfloat16& h, __nv_bfloat16& l) {
    h = __float2bfloat16_rn(v);
    l = __float2bfloat16_rn(v - __bfloat162float(h));
}
__device__ __forceinline__ uint32_t pack_bf2(__nv_bfloat16 a, __nv_bfloat16 b) {
    __nv_bfloat162 p = __nv_bfloat162(a, b);
    return *(uint32_t*)&p;
}
__device__ __forceinline__ int warp_iscan(int v, int lane) {
#pragma unroll
    for (int off = 1; off < 32; off <<= 1) {
        int u = __shfl_up_sync(0xffffffffu, v, off);
        if (lane >= off) v += u;
    }
    return v;
}

// ---------------- edge index access (int64 or int32, runtime-detected) ----
__device__ __forceinline__ int edst(const void* ei, int e) {
    return g_is64 ? (int)((const long long*)ei)[(size_t)N_EDGES + e]
                  : ((const int*)ei)[(size_t)N_EDGES + e];
}
__device__ __forceinline__ int esrc(const void* ei, int e) {
    return g_is64 ? (int)((const long long*)ei)[e] : ((const int*)ei)[e];
}

// init degrees + dtype detect + weight split + x->fp16 conversion
__global__ void k_init(const int* ei, const float* __restrict__ x,
                       const float* __restrict__ W1l, const float* __restrict__ W1r,
                       const float* __restrict__ W2l, const float* __restrict__ W2r) {
    int i = blockIdx.x * blockDim.x + threadIdx.x;
    if (i < N_NODES) g_deg[i] = 0;
    if (i < N_NODES * 32) {
        int n = i >> 5, q = i & 31;
        float2 v = *(const float2*)&x[(size_t)n * DIN + 2 * q];
        __half2 h = __floats2half2_rn(v.x, v.y);
        g_xh[(size_t)n * 32 + q] = *(uint32_t*)&h;
    }
    int tot1 = DHID * 64;
    if (i < tot1) {
        int o = i >> 6, c = 2 * (i & 63);
        float v0 = (c < 64) ? W1l[o * 64 + c] : W1r[o * 64 + c - 64];
        float v1 = (c < 64) ? W1l[o * 64 + c + 1] : W1r[o * 64 + c - 63];
        __nv_bfloat16 h0, h1, l0, l1;
        split_bf16(v0, h0, l0); split_bf16(v1, h1, l1);
        g_w1h[i] = pack_bf2(h0, h1);
        g_w1l[i] = pack_bf2(l0, l1);
    } else if (i < tot1 + W2ROWS * 64) {
        int j = i - tot1;
        int o = j >> 6, c = 2 * (j & 63);
        float v0 = (o < DOUT) ? W2l[o * DHID + c] : W2r[(o - DOUT) * DHID + c];
        float v1 = (o < DOUT) ? W2l[o * DHID + c + 1] : W2r[(o - DOUT) * DHID + c + 1];
        __nv_bfloat16 h0, h1, l0, l1;
        split_bf16(v0, h0, l0); split_bf16(v1, h1, l1);
        g_w2h[j] = pack_bf2(h0, h1);
        g_w2l[j] = pack_bf2(l0, l1);
    }
    if (blockIdx.x == 0) {
        bool ok = true;
        for (int j = threadIdx.x; j < 4096; j += blockDim.x)
            if (ei[2 * j + 1] != 0) ok = false;
        int all = __syncthreads_and((int)ok);
        if (threadIdx.x == 0) g_is64 = all ? 1 : 0;
    }
}
__global__ void k_hist(const void* ei) {
    int e = blockIdx.x * blockDim.x + threadIdx.x;
    if (e < N_EDGES) atomicAdd(&g_deg[edst(ei, e)], 1);
}
// shuffle scan: 2 barriers instead of 16
__global__ void k_scan_block() {
    __shared__ int ws[16];
    int tid = threadIdx.x, lane = tid & 31, w = tid >> 5;
    int i = blockIdx.x * SCAN_B + tid;
    int v = (i < N_NODES) ? g_deg[i] : 0;
    int inc = warp_iscan(v, lane);
    if (lane == 31) ws[w] = inc;
    __syncthreads();
    if (w == 0) {
        int u = (lane < 16) ? ws[lane] : 0;
        u = warp_iscan(u, lane);
        if (lane < 16) ws[lane] = u;
    }
    __syncthreads();
    int woff = (w == 0) ? 0 : ws[w - 1];
    if (i < N_NODES) g_rowptr[i] = woff + inc - v;  // exclusive
    if (tid == SCAN_B - 1) g_part[blockIdx.x] = woff + inc;
}
// each block redundantly shuffle-scans the partials, then applies offset
__global__ void k_scan_add() {
    __shared__ int sp[256];
    __shared__ int ws[8];
    int t = threadIdx.x, lane = t & 31, w = t >> 5;
    int inc = 0, v = 0;
    if (t < 256) {
        v = (t < SCAN_NB) ? g_part[t] : 0;
        inc = warp_iscan(v, lane);
        if (lane == 31) ws[w] = inc;
    }
    __syncthreads();
    if (w == 0) {
        int u = (lane < 8) ? ws[lane] : 0;
        u = warp_iscan(u, lane);
        if (lane < 8) ws[lane] = u;
    }
    __syncthreads();
    if (t < 256) sp[t] = inc + ((w == 0) ? 0 : ws[w - 1]);
    __syncthreads();
    int offset = (blockIdx.x == 0) ? 0 : sp[blockIdx.x - 1];
    int i = blockIdx.x * SCAN_B + t;
    if (i < N_NODES) {
        int r = g_rowptr[i] + offset;
        g_rowptr[i] = r;
        g_fill[i] = r;
    }
    if (i == 0) g_rowptr[N_NODES] = N_EDGES;
}
__global__ void k_scatter(const void* ei) {
    int e = blockIdx.x * blockDim.x + threadIdx.x;
    if (e < N_EDGES) {
        int d = edst(ei, e);
        int p = atomicAdd(&g_fill[d], 1);
        g_col[p] = esrc(ei, e);
    }
}

// ---------------- k_agg: 2 nodes per warp, half-warp per node ------------
// Lane (hl = lane&15) covers col quad (4hl..4hl+3) via one uint2 per edge.
// 8 edges in flight per warp (2 nodes x 4-deep unroll).
__global__ void __launch_bounds__(256) k_agg() {
    int warp = (blockIdx.x * blockDim.x + threadIdx.x) >> 5;
    int lane = threadIdx.x & 31;
    int half = lane >> 4, hl = lane & 15;
    int n = 2 * warp + half;
    if (n >= N_NODES) return;
    float a0 = 0.f, a1 = 0.f, a2 = 0.f, a3 = 0.f;
    float b0 = 0.f, b1v = 0.f, b2v = 0.f, b3 = 0.f;
    float c0 = 0.f, c1 = 0.f, c2 = 0.f, c3 = 0.f;
    float d0 = 0.f, d1 = 0.f, d2 = 0.f, d3 = 0.f;
    int s0 = g_rowptr[n], s1 = g_rowptr[n + 1];
    int e = s0;
    for (; e + 3 < s1; e += 4) {
        uint2 p0 = *(const uint2*)(g_xh + (size_t)g_col[e] * 32 + 2 * hl);
        uint2 p1 = *(const uint2*)(g_xh + (size_t)g_col[e + 1] * 32 + 2 * hl);
        uint2 p2 = *(const uint2*)(g_xh + (size_t)g_col[e + 2] * 32 + 2 * hl);
        uint2 p3 = *(const uint2*)(g_xh + (size_t)g_col[e + 3] * 32 + 2 * hl);
        float2 f;
        f = __half22float2(*(__half2*)&p0.x); a0 += f.x; a1 += f.y;
        f = __half22float2(*(__half2*)&p0.y); a2 += f.x; a3 += f.y;
        f = __half22float2(*(__half2*)&p1.x); b0 += f.x; b1v += f.y;
        f = __half22float2(*(__half2*)&p1.y); b2v += f.x; b3 += f.y;
        f = __half22float2(*(__half2*)&p2.x); c0 += f.x; c1 += f.y;
        f = __half22float2(*(__half2*)&p2.y); c2 += f.x; c3 += f.y;
        f = __half22float2(*(__half2*)&p3.x); d0 += f.x; d1 += f.y;
        f = __half22float2(*(__half2*)&p3.y); d2 += f.x; d3 += f.y;
    }
    for (; e < s1; e++) {
        uint2 p0 = *(const uint2*)(g_xh + (size_t)g_col[e] * 32 + 2 * hl);
        float2 f;
        f = __half22float2(*(__half2*)&p0.x); a0 += f.x; a1 += f.y;
        f = __half22float2(*(__half2*)&p0.y); a2 += f.x; a3 += f.y;
    }
    a0 += b0 + c0 + d0;
    a1 += b1v + c1 + d1;
    a2 += b2v + c2 + d2;
    a3 += b3 + c3 + d3;
    float inv = 1.f / (float)max(s1 - s0, 1);
    a0 *= inv; a1 *= inv; a2 *= inv; a3 *= inv;
    __nv_bfloat16 h0, l0, h1, l1, h2, l2, h3, l3;
    split_bf16(a0, h0, l0); split_bf16(a1, h1, l1);
    split_bf16(a2, h2, l2); split_bf16(a3, h3, l3);
    uint2 oh = make_uint2(pack_bf2(h0, h1), pack_bf2(h2, h3));
    uint2 ol = make_uint2(pack_bf2(l0, l1), pack_bf2(l2, l3));
    *(uint2*)(g_ah + (size_t)n * 32 + 2 * hl) = oh;
    *(uint2*)(g_al + (size_t)n * 32 + 2 * hl) = ol;
}

// ---------------- k_mma: PERSISTENT; weights staged once, loop tiles ------
__global__ void __launch_bounds__(512) k_mma(const float* __restrict__ b1) {
    extern __shared__ char dsm[];
    __nv_bfloat16* sAh = (__nv_bfloat16*)(dsm + SM_AH);
    __nv_bfloat16* sAl = (__nv_bfloat16*)(dsm + SM_AL);
    __nv_bfloat16* sW1h = (__nv_bfloat16*)(dsm + SM_W1H);
    __nv_bfloat16* sW1l = (__nv_bfloat16*)(dsm + SM_W1L);
    __nv_bfloat16* sW2h = (__nv_bfloat16*)(dsm + SM_W2H);
    __nv_bfloat16* sW2l = (__nv_bfloat16*)(dsm + SM_W2L);
    float* sB = (float*)(dsm + SM_BIAS);

    int tid = threadIdx.x, wid = tid >> 5, lane = tid & 31;

    // ---- stage weights ONCE ----
    for (int i = tid; i < 128 * 16; i += 512) {
        int r = i >> 4, c8 = i & 15;
        *(uint4*)((char*)sW1h + r * (LDS_ROW * 2) + c8 * 16) = *(const uint4*)(g_w1h + r * 64 + c8 * 4);
        *(uint4*)((char*)sW1l + r * (LDS_ROW * 2) + c8 * 16) = *(const uint4*)(g_w1l + r * 64 + c8 * 4);
    }
    for (int i = tid; i < W2ROWS * 16; i += 512) {
        int r = i >> 4, c8 = i & 15;
        *(uint4*)((char*)sW2h + r * (LDS_ROW * 2) + c8 * 16) = *(const uint4*)(g_w2h + r * 64 + c8 * 4);
        *(uint4*)((char*)sW2l + r * (LDS_ROW * 2) + c8 * 16) = *(const uint4*)(g_w2l + r * 64 + c8 * 4);
    }
    if (tid < DHID) sB[tid] = b1[tid];

    // warp-tile coordinates (constant across tiles)
    int Rb = (wid & 3) * 32;
    int Nb = (wid >> 2) * 32;
    int Rb2 = (wid & 7) * 16;
    int Nb2 = (wid >> 3) * 40;
    int qr = lane >> 2;
    int qc = 2 * (lane & 3);

    for (int tile = blockIdx.x; tile < N_TILES; tile += MMA_GRID) {
        int base = tile * TILE_M;
        __syncthreads();  // prev tile fully consumed before overwriting A
        // ---- stage A tile: agg half from g_ah/g_al, self half from g_xh ----
        for (int i = tid; i < 128 * 8; i += 512) {
            int r = i >> 3, c8 = i & 7;
            int n = base + r;
            uint4 vh = make_uint4(0, 0, 0, 0), vl = make_uint4(0, 0, 0, 0);
            if (n < N_NODES) {
                vh = *(const uint4*)(g_ah + (size_t)n * 32 + c8 * 4);
                vl = *(const uint4*)(g_al + (size_t)n * 32 + c8 * 4);
            }
            *(uint4*)((char*)sAh + r * (LDS_ROW * 2) + c8 * 16) = vh;
            *(uint4*)((char*)sAl + r * (LDS_ROW * 2) + c8 * 16) = vl;
        }
        // self half: split fp16 x on the fly into cols 64..127
        for (int i = tid; i < 128 * 16; i += 512) {
            int r = i >> 4, q2 = i & 15;  // q2: pair of half2 words
            int n = base + r;
            uint2 p = make_uint2(0, 0);
            if (n < N_NODES) p = *(const uint2*)(g_xh + (size_t)n * 32 + 2 * q2);
            float2 f0 = __half22float2(*(__half2*)&p.x);
            float2 f1 = __half22float2(*(__half2*)&p.y);
            __nv_bfloat16 h0, l0, h1, l1, h2, l2, h3, l3;
            split_bf16(f0.x, h0, l0); split_bf16(f0.y, h1, l1);
            split_bf16(f1.x, h2, l2); split_bf16(f1.y, h3, l3);
            uint2 oh = make_uint2(pack_bf2(h0, h1), pack_bf2(h2, h3));
            uint2 ol = make_uint2(pack_bf2(l0, l1), pack_bf2(l2, l3));
            *(uint2*)(sAh + r * LDS_ROW + 64 + 4 * q2) = oh;
            *(uint2*)(sAl + r * LDS_ROW + 64 + 4 * q2) = ol;
        }
        __syncthreads();

        // ---- GEMM1: 128x128, warp grid 4(M) x 4(N), warp tile 32x32 ----
        float acc[2][4][4];
#pragma unroll
        for (int mt = 0; mt < 2; mt++)
#pragma unroll
            for (int nt = 0; nt < 4; nt++)
#pragma unroll
                for (int j = 0; j < 4; j++) acc[mt][nt][j] = 0.f;

        for (int ks = 0; ks < 8; ks++) {
            int kc = ks * 16 + qc;
            uint32_t ah[2][4], al[2][4];
#pragma unroll
            for (int mt = 0; mt < 2; mt++) {
                int r = Rb + mt * 16 + qr;
                ah[mt][0] = *(const uint32_t*)(sAh + r * LDS_ROW + kc);
                ah[mt][1] = *(const uint32_t*)(sAh + (r + 8) * LDS_ROW + kc);
                ah[mt][2] = *(const uint32_t*)(sAh + r * LDS_ROW + kc + 8);
                ah[mt][3] = *(const uint32_t*)(sAh + (r + 8) * LDS_ROW + kc + 8);
                al[mt][0] = *(const uint32_t*)(sAl + r * LDS_ROW + kc);
                al[mt][1] = *(const uint32_t*)(sAl + (r + 8) * LDS_ROW + kc);
                al[mt][2] = *(const uint32_t*)(sAl + r * LDS_ROW + kc + 8);
                al[mt][3] = *(const uint32_t*)(sAl + (r + 8) * LDS_ROW + kc + 8);
            }
#pragma unroll
            for (int nt = 0; nt < 4; nt++) {
                int nn = Nb + nt * 8 + qr;
                uint32_t bh0 = *(const uint32_t*)(sW1h + nn * LDS_ROW + kc);
                uint32_t bh1 = *(const uint32_t*)(sW1h + nn * LDS_ROW + kc + 8);
                uint32_t bl0 = *(const uint32_t*)(sW1l + nn * LDS_ROW + kc);
                uint32_t bl1 = *(const uint32_t*)(sW1l + nn * LDS_ROW + kc + 8);
#pragma unroll
                for (int mt = 0; mt < 2; mt++) {
                    mma16816(acc[mt][nt], ah[mt], bh0, bh1);
                    mma16816(acc[mt][nt], al[mt], bh0, bh1);
                    mma16816(acc[mt][nt], ah[mt], bl0, bl1);
                }
            }
        }
        __syncthreads();  // done reading A; safe to overwrite with h1

        // ---- epilogue 1: bias + relu + resplit -> sAh/sAl (h1 tile) ----
#pragma unroll
        for (int mt = 0; mt < 2; mt++) {
#pragma unroll
            for (int nt = 0; nt < 4; nt++) {
                int c = Nb + nt * 8 + qc;
                float bv0 = sB[c], bv1 = sB[c + 1];
#pragma unroll
                for (int half = 0; half < 2; half++) {
                    int r = Rb + mt * 16 + qr + half * 8;
                    float v0 = acc[mt][nt][2 * half] + bv0;
                    float v1 = acc[mt][nt][2 * half + 1] + bv1;
                    v0 = v0 > 0.f ? v0 : 0.f;
                    v1 = v1 > 0.f ? v1 : 0.f;
                    __nv_bfloat16 h0, h1, l0, l1;
                    split_bf16(v0, h0, l0);
                    split_bf16(v1, h1, l1);
                    *(uint32_t*)(sAh + r * LDS_ROW + c) = pack_bf2(h0, h1);
                    *(uint32_t*)(sAl + r * LDS_ROW + c) = pack_bf2(l0, l1);
                }
            }
        }
        __syncthreads();

        // ---- GEMM2: 128x80, warp grid 8(M) x 2(N), warp tile 16x40 ----
        float acc2[5][4];
#pragma unroll
        for (int nt = 0; nt < 5; nt++)
#pragma unroll
            for (int j = 0; j < 4; j++) acc2[nt][j] = 0.f;

        for (int ks = 0; ks < 8; ks++) {
            int kc = ks * 16 + qc;
            int r = Rb2 + qr;
            uint32_t ah[4], al[4];
            ah[0] = *(const uint32_t*)(sAh + r * LDS_ROW + kc);
            ah[1] = *(const uint32_t*)(sAh + (r + 8) * LDS_ROW + kc);
            ah[2] = *(const uint32_t*)(sAh + r * LDS_ROW + kc + 8);
            ah[3] = *(const uint32_t*)(sAh + (r + 8) * LDS_ROW + kc + 8);
            al[0] = *(const uint32_t*)(sAl + r * LDS_ROW + kc);
            al[1] = *(const uint32_t*)(sAl + (r + 8) * LDS_ROW + kc);
            al[2] = *(const uint32_t*)(sAl + r * LDS_ROW + kc + 8);
            al[3] = *(const uint32_t*)(sAl + (r + 8) * LDS_ROW + kc + 8);
#pragma unroll
            for (int nt = 0; nt < 5; nt++) {
                int nn = Nb2 + nt * 8 + qr;
                uint32_t bh0 = *(const uint32_t*)(sW2h + nn * LDS_ROW + kc);
                uint32_t bh1 = *(const uint32_t*)(sW2h + nn * LDS_ROW + kc + 8);
                uint32_t bl0 = *(const uint32_t*)(sW2l + nn * LDS_ROW + kc);
                uint32_t bl1 = *(const uint32_t*)(sW2l + nn * LDS_ROW + kc + 8);
                mma16816(acc2[nt], ah, bh0, bh1);
                mma16816(acc2[nt], al, bh0, bh1);
                mma16816(acc2[nt], ah, bl0, bl1);
            }
        }

        // ---- epilogue 2: write y2l (half2) / y2r (fp32) ----
#pragma unroll
        for (int nt = 0; nt < 5; nt++) {
            int c = Nb2 + nt * 8 + qc;  // 0..78 even
            int n0 = base + Rb2 + qr;
            int n1 = n0 + 8;
            if (c < DOUT) {
                __half2 h0 = __floats2half2_rn(acc2[nt][0], acc2[nt][1]);
                __half2 h1 = __floats2half2_rn(acc2[nt][2], acc2[nt][3]);
                if (n0 < N_NODES) g_y2l[(size_t)n0 * Y2L_W32 + (c >> 1)] = *(uint32_t*)&h0;
                if (n1 < N_NODES) g_y2l[(size_t)n1 * Y2L_W32 + (c >> 1)] = *(uint32_t*)&h1;
            } else {
                int cc = c - DOUT;
                if (n0 < N_NODES)
                    *(float2*)&g_y2r[(size_t)n0 * DOUT + cc] = make_float2(acc2[nt][0], acc2[nt][1]);
                if (n1 < N_NODES)
                    *(float2*)&g_y2r[(size_t)n1 * DOUT + cc] = make_float2(acc2[nt][2], acc2[nt][3]);
            }
        }
    }
}

// ---------------- final: out = log_softmax(mean-agg(y2l) + b2 + y2r) ------
// 2 nodes per warp, half-warp per node; lane hl<10 owns output quad
// (4hl..4hl+3) via one uint2 per edge; 8 edges in flight per warp.
__global__ void __launch_bounds__(256) k_out(const float* __restrict__ b2,
                                             float* __restrict__ out) {
    int warp = (blockIdx.x * blockDim.x + threadIdx.x) >> 5;
    int lane = threadIdx.x & 31;
    int half = lane >> 4, hl = lane & 15;
    int n = 2 * warp + half;
    if (n >= N_NODES) return;
    int ln = (hl < 10) ? 2 * hl : 0;  // y2l word offset (pads read col 0)
    float a0 = 0.f, a1 = 0.f, a2 = 0.f, a3 = 0.f;
    float b0 = 0.f, b1v = 0.f, b2v = 0.f, b3 = 0.f;
    float c0 = 0.f, c1 = 0.f, c2 = 0.f, c3 = 0.f;
    float d0 = 0.f, d1 = 0.f, d2 = 0.f, d3 = 0.f;
    int s0 = g_rowptr[n], s1 = g_rowptr[n + 1];
    int e = s0;
    for (; e + 3 < s1; e += 4) {
        uint2 p0 = *(const uint2*)(g_y2l + (size_t)g_col[e] * Y2L_W32 + ln);
        uint2 p1 = *(const uint2*)(g_y2l + (size_t)g_col[e + 1] * Y2L_W32 + ln);
        uint2 p2 = *(const uint2*)(g_y2l + (size_t)g_col[e + 2] * Y2L_W32 + ln);
        uint2 p3 = *(const uint2*)(g_y2l + (size_t)g_col[e + 3] * Y2L_W32 + ln);
        float2 f;
        f = __half22float2(*(__half2*)&p0.x); a0 += f.x; a1 += f.y;
        f = __half22float2(*(__half2*)&p0.y); a2 += f.x; a3 += f.y;
        f = __half22float2(*(__half2*)&p1.x); b0 += f.x; b1v += f.y;
        f = __half22float2(*(__half2*)&p1.y); b2v += f.x; b3 += f.y;
        f = __half22float2(*(__half2*)&p2.x); c0 += f.x; c1 += f.y;
        f = __half22float2(*(__half2*)&p2.y); c2 += f.x; c3 += f.y;
        f = __half22float2(*(__half2*)&p3.x); d0 += f.x; d1 += f.y;
        f = __half22float2(*(__half2*)&p3.y); d2 += f.x; d3 += f.y;
    }
    for (; e < s1; e++) {
        uint2 p0 = *(const uint2*)(g_y2l + (size_t)g_col[e] * Y2L_W32 + ln);
        float2 f;
        f = __half22float2(*(__half2*)&p0.x); a0 += f.x; a1 += f.y;
        f = __half22float2(*(__half2*)&p0.y); a2 += f.x; a3 += f.y;
    }
    a0 += b0 + c0 + d0;
    a1 += b1v + c1 + d1;
    a2 += b2v + c2 + d2;
    a3 += b3 + c3 + d3;
    float inv = 1.f / (float)max(s1 - s0, 1);
    float v0 = -INFINITY, v1 = -INFINITY, v2 = -INFINITY, v3 = -INFINITY;
    if (hl < 10) {
        int c = 4 * hl;
        float4 yr = *(const float4*)&g_y2r[(size_t)n * DOUT + c];
        float4 bb = *(const float4*)&b2[c];
        v0 = a0 * inv + bb.x + yr.x;
        v1 = a1 * inv + bb.y + yr.y;
        v2 = a2 * inv + bb.z + yr.z;
        v3 = a3 * inv + bb.w + yr.w;
    }
    float m = fmaxf(fmaxf(v0, v1), fmaxf(v2, v3));
#pragma unroll
    for (int off = 8; off; off >>= 1)
        m = fmaxf(m, __shfl_xor_sync(0xffffffffu, m, off));
    float s = (hl < 10)
                  ? (expf(v0 - m) + expf(v1 - m) + expf(v2 - m) + expf(v3 - m))
                  : 0.f;
#pragma unroll
    for (int off = 8; off; off >>= 1)
        s += __shfl_xor_sync(0xffffffffu, s, off);
    float lse = m + logf(s);
    if (hl < 10) {
        float4 o = make_float4(v0 - lse, v1 - lse, v2 - lse, v3 - lse);
        *(float4*)&out[(size_t)n * DOUT + 4 * hl] = o;
    }
}

// ---------------- launch --------------------------------------------------
extern "C" void kernel_launch(void* const* d_in, const int* in_sizes, int n_in,
                              void* d_out, int out_size) {
    const float* x = (const float*)d_in[0];
    const void* ei = d_in[1];
    const float* W1l = (const float*)d_in[2];
    const float* b1 = (const float*)d_in[3];
    const float* W1r = (const float*)d_in[4];
    const float* W2l = (const float*)d_in[5];
    const float* b2 = (const float*)d_in[6];
    const float* W2r = (const float*)d_in[7];
    float* out = (float*)d_out;

    cudaFuncSetAttribute(k_mma, cudaFuncAttributeMaxDynamicSharedMemorySize,
                         SM_TOTAL);

    k_init<<<(N_NODES * 32 + 255) / 256, 256>>>((const int*)ei, x, W1l, W1r, W2l, W2r);
    k_hist<<<(N_EDGES + 255) / 256, 256>>>(ei);
    k_scan_block<<<SCAN_NB, SCAN_B>>>();
    k_scan_add<<<SCAN_NB, SCAN_B>>>();
    k_scatter<<<(N_EDGES + 255) / 256, 256>>>(ei);

    k_agg<<<(N_NODES * 16 + 255) / 256, 256>>>();
    k_mma<<<MMA_GRID, 512, SM_TOTAL>>>(b1);
    k_out<<<(N_NODES * 16 + 255) / 256, 256>>>(b2, out);
}